// round 11
// baseline (speedup 1.0000x reference)
#include <cuda_runtime.h>
#include <cuda_bf16.h>
#include <math_constants.h>

#define NN 40000
#define NE 320000

// ---------------- scratch (device globals; no allocation allowed) ----------------
__device__ float fG[NN * 32];
__device__ float scoresG[NE * 4];
__device__ float vG[NE * 32];
__device__ float smaxG[NN * 4];
__device__ float accG[NN * 48];   // per (n,h): [0..7]=num, [8]=den, pad
// w2 split bf16, j-major fragment layout: uint4 = (hi_b0, hi_b1, lo_b0, lo_b1)
// ntile t = j*3 + ig (i = ig*8 + g); index = ((t*4 + ks)*32 + lane)
__device__ uint4 w2pG[96 * 4 * 32];
// w1 split bf16 fragment layout: index = ((nt*2 + ks)*32 + lane)
__device__ uint4 w1pG[16 * 32];

__device__ __forceinline__ void atomicMaxF(float* a, float v) {
    if (v == 0.0f) v = 0.0f;
    if (v >= 0.0f) atomicMax((int*)a, __float_as_int(v));
    else           atomicMin((unsigned int*)a, __float_as_uint(v));
}

__device__ __forceinline__ void redAdd4(float* p, float a, float b, float c, float d) {
    asm volatile("red.global.add.v4.f32 [%0], {%1,%2,%3,%4};"
                 :: "l"(p), "f"(a), "f"(b), "f"(c), "f"(d) : "memory");
}

__device__ __forceinline__ void mma_bf16(float* c, const unsigned* a, unsigned b0, unsigned b1) {
    asm volatile("mma.sync.aligned.m16n8k16.row.col.f32.bf16.bf16.f32 "
                 "{%0,%1,%2,%3}, {%4,%5,%6,%7}, {%8,%9}, {%0,%1,%2,%3};\n"
                 : "+f"(c[0]), "+f"(c[1]), "+f"(c[2]), "+f"(c[3])
                 : "r"(a[0]), "r"(a[1]), "r"(a[2]), "r"(a[3]), "r"(b0), "r"(b1));
}

// packed fp32x2 helpers (sm_100a FFMA2 path)
__device__ __forceinline__ unsigned long long packf2(float x, float y) {
    unsigned long long r;
    asm("mov.b64 %0, {%1,%2};" : "=l"(r) : "f"(x), "f"(y));
    return r;
}
__device__ __forceinline__ float2 unpackf2(unsigned long long v) {
    float2 r;
    asm("mov.b64 {%0,%1}, %2;" : "=f"(r.x), "=f"(r.y) : "l"(v));
    return r;
}
__device__ __forceinline__ void ffma2(unsigned long long& d, unsigned long long a, unsigned long long b) {
    asm("fma.rn.f32x2 %0, %1, %2, %0;" : "+l"(d) : "l"(a), "l"(b));
}

__device__ __forceinline__ void splitpack(float a, float b, unsigned& hi, unsigned& lo) {
    __nv_bfloat16 ha = __float2bfloat16_rn(a), hb = __float2bfloat16_rn(b);
    __nv_bfloat16 la = __float2bfloat16_rn(a - __bfloat162float(ha));
    __nv_bfloat16 lb = __float2bfloat16_rn(b - __bfloat162float(hb));
    hi = ((unsigned)__bfloat16_as_ushort(hb) << 16) | (unsigned)__bfloat16_as_ushort(ha);
    lo = ((unsigned)__bfloat16_as_ushort(lb) << 16) | (unsigned)__bfloat16_as_ushort(la);
}

// ---------------- merged setup: prep_w2 | prep_w1 | init | node_ln ----------------
#define SETUP_P2   (768 * 32)              // 24576
#define SETUP_P1   512
__global__ void setup_kernel(const float* __restrict__ w2, const float* __restrict__ w1,
                             const float* __restrict__ features,
                             const float* __restrict__ ln_w, const float* __restrict__ ln_b,
                             int N) {
    int base = blockIdx.x * 256 + threadIdx.x;
    if (base < SETUP_P2) {
        int idx = base;
        int o = idx >> 5, kp = idx & 31;
        unsigned hiu, lou;
        splitpack(w2[o * 64 + 2 * kp], w2[o * 64 + 2 * kp + 1], hiu, lou);
        int i = o >> 5, j = o & 31;
        int tt = j * 3 + (i >> 3);
        int g = i & 7;
        int ks = kp >> 3;
        int tq = kp & 3;
        int half = (kp >> 2) & 1;
        int frag = (tt * 4 + ks) * 32 + g * 4 + tq;
        ((unsigned*)w2pG)[frag * 4 + half]     = hiu;
        ((unsigned*)w2pG)[frag * 4 + 2 + half] = lou;
        return;
    }
    base -= SETUP_P2;
    if (base < SETUP_P1) {
        int idx = base;
        int lane = idx & 31, ksnt = idx >> 5;
        int ks = ksnt & 1, nt = ksnt >> 1;
        int g = lane >> 2, tq = lane & 3;
        int j = nt * 8 + g;
        int k0 = ks * 16 + 2 * tq;
        unsigned h0, l0, h1, l1;
        splitpack(w1[j * 32 + k0],     w1[j * 32 + k0 + 1],     h0, l0);
        splitpack(w1[j * 32 + k0 + 8], w1[j * 32 + k0 + 8 + 1], h1, l1);
        w1pG[(nt * 2 + ks) * 32 + lane] = make_uint4(h0, h1, l0, l1);
        return;
    }
    base -= SETUP_P1;
    if (base < N * 48) {
        if (base < N * 4) smaxG[base] = -CUDART_INF_F;
        accG[base] = 0.0f;
        return;
    }
    base -= N * 48;
    if (base < N) {
        int n = base;
        float f[32];
        const float4* fp = (const float4*)(features + (size_t)n * 32);
#pragma unroll
        for (int q = 0; q < 8; q++) {
            float4 v = fp[q];
            f[q * 4 + 0] = v.x; f[q * 4 + 1] = v.y; f[q * 4 + 2] = v.z; f[q * 4 + 3] = v.w;
        }
        float nf[16];
#pragma unroll
        for (int m = 0; m < 8; m++) {
            nf[2 * m]     = sqrtf(f[m * 4] * f[m * 4]);
            nf[2 * m + 1] = sqrtf(f[m * 4 + 1] * f[m * 4 + 1] +
                                  f[m * 4 + 2] * f[m * 4 + 2] +
                                  f[m * 4 + 3] * f[m * 4 + 3]);
        }
        float ratio[16];
#pragma unroll
        for (int g = 0; g < 2; g++) {
            float mu = 0.0f;
#pragma unroll
            for (int b = 0; b < 8; b++) mu += nf[8 * g + b];
            mu *= 0.125f;
            float var = 0.0f;
#pragma unroll
            for (int b = 0; b < 8; b++) { float d = nf[8 * g + b] - mu; var += d * d; }
            var *= 0.125f;
            float rs = rsqrtf(var + 1e-5f);
#pragma unroll
            for (int b = 0; b < 8; b++) {
                float l = (nf[8 * g + b] - mu) * rs * ln_w[b] + ln_b[b];
                l = fmaxf(l, 0.0f);
                ratio[8 * g + b] = l / (nf[8 * g + b] + 1e-8f);
            }
        }
        float4* op = (float4*)(fG + (size_t)n * 32);
#pragma unroll
        for (int m = 0; m < 8; m++) {
            float4 v;
            v.x = f[m * 4 + 0] * ratio[2 * m];
            v.y = f[m * 4 + 1] * ratio[2 * m + 1];
            v.z = f[m * 4 + 2] * ratio[2 * m + 1];
            v.w = f[m * 4 + 3] * ratio[2 * m + 1];
            op[m] = v;
        }
    }
}

// ---------------- fused per-edge kernel: 128 edges / 384 threads (12 warps, 1 block/SM) ----------------
// smem layout (float/uint word indices)
#define SB2   0       // 768
#define STMP  768     // 128*132 = 16896 -> 17664
#define SH2H  17664   // 128*36 uints -> 22272
#define SH2L  22272   // -> 26880
#define SSRC  26880   // 128 -> 27008
#define SSTG  27008
#define SEF   (SSTG)          // 128*32 = 4096
#define SFU   (SSTG + 4096)   // 128*32 = 4096
#define SBAS  (SSTG + 8192)   // 128*64 = 8192
#define SCONV (SSTG)          // 128*68 = 8704 <= 16384 (staging dead by then)
#define STOT  43392           // 173568 bytes

__global__ __launch_bounds__(384, 1)
void edge_kernel(const int* __restrict__ src, const int* __restrict__ dst,
                 const float* __restrict__ basis, const float* __restrict__ edge_feats,
                 const float* __restrict__ b1, const float* __restrict__ b2, int E) {
    extern __shared__ float sm[];
    unsigned* smu = (unsigned*)sm;
    int t = threadIdx.x;
    int e0 = blockIdx.x * 128;
    int w = t >> 5, lane = t & 31, g = lane >> 2, tq = lane & 3;

    // ---- stage b2, src, then per-edge inputs ----
    if (t < 128) {
        int ee = e0 + t;
        ((int*)&sm[SSRC])[t] = __ldg(src + (ee < E ? ee : E - 1));
    }
    for (int idx = t; idx < 768; idx += 384) sm[SB2 + idx] = b2[idx];
    __syncthreads();

    for (int idx = t; idx < 1024; idx += 384) {
        int el = idx >> 3, q = idx & 7;
        int ee = e0 + el; int ec = ee < E ? ee : E - 1;
        *(float4*)&sm[SEF + el * 32 + q * 4] =
            __ldg((const float4*)edge_feats + (size_t)ec * 8 + q);
        int s = ((const int*)&sm[SSRC])[el];
        *(float4*)&sm[SFU + el * 32 + q * 4] = ((const float4*)fG)[(size_t)s * 8 + q];
    }
    for (int idx = t; idx < 2048; idx += 384) {
        int el = idx >> 4, q = idx & 15;
        int ee = e0 + el; int ec = ee < E ? ee : E - 1;
        *(float4*)&sm[SBAS + el * 64 + q * 4] =
            __ldg((const float4*)basis + (size_t)ec * 16 + q);
    }
    __syncthreads();

    // ---- phase A1: tmp = fU x basis (vectorized float4 LDS) ----
    for (int idx = t; idx < 4096; idx += 384) {
        int el = idx >> 5, j = idx & 31;
        int m = j >> 2, pp = j & 3;
        float4 fv = *(const float4*)&sm[SFU + el * 32 + m * 4];
        float4 r0 = *(const float4*)&sm[SBAS + el * 64 + 0 * 16 + pp * 4];
        float4 r1 = *(const float4*)&sm[SBAS + el * 64 + 1 * 16 + pp * 4];
        float4 r2 = *(const float4*)&sm[SBAS + el * 64 + 2 * 16 + pp * 4];
        float4 r3 = *(const float4*)&sm[SBAS + el * 64 + 3 * 16 + pp * 4];
        float o0 = fv.x * r0.x + fv.y * r1.x + fv.z * r2.x + fv.w * r3.x;
        float o1 = fv.x * r0.y + fv.y * r1.y + fv.z * r2.y + fv.w * r3.y;
        float o2 = fv.x * r0.z + fv.y * r1.z + fv.z * r2.z + fv.w * r3.z;
        float o3 = fv.x * r0.w + fv.y * r1.w + fv.z * r2.w + fv.w * r3.w;
        *(float4*)&sm[STMP + el * 132 + j * 4] = make_float4(o0, o1, o2, o3);
    }

    // ---- phase A2: h = relu(ef@w1^T + b1) via split-bf16 MMA (64 (mt,nt) pairs, 12 warps) ----
    {
        int cur_mt = -1;
        unsigned eAh[2][4], eAl[2][4];
#pragma unroll
        for (int it = 0; it < 6; it++) {
            int p = w + it * 12;                  // 64 pairs total (8 mt x 8 nt)
            if (p < 64) {
                int mt = p >> 3, nt = p & 7;
                if (mt != cur_mt) {
                    cur_mt = mt;
#pragma unroll
                    for (int ks = 0; ks < 2; ks++) {
                        float2 x0 = *(const float2*)&sm[SEF + (mt * 16 + g) * 32 + ks * 16 + 2 * tq];
                        float2 x1 = *(const float2*)&sm[SEF + (mt * 16 + g + 8) * 32 + ks * 16 + 2 * tq];
                        float2 x2 = *(const float2*)&sm[SEF + (mt * 16 + g) * 32 + ks * 16 + 8 + 2 * tq];
                        float2 x3 = *(const float2*)&sm[SEF + (mt * 16 + g + 8) * 32 + ks * 16 + 8 + 2 * tq];
                        splitpack(x0.x, x0.y, eAh[ks][0], eAl[ks][0]);
                        splitpack(x1.x, x1.y, eAh[ks][1], eAl[ks][1]);
                        splitpack(x2.x, x2.y, eAh[ks][2], eAl[ks][2]);
                        splitpack(x3.x, x3.y, eAh[ks][3], eAl[ks][3]);
                    }
                }
                float2 bb = __ldg((const float2*)(b1 + nt * 8 + 2 * tq));
                float acc[4] = {bb.x, bb.y, bb.x, bb.y};
#pragma unroll
                for (int ks = 0; ks < 2; ks++) {
                    uint4 bv = __ldg(w1pG + (nt * 2 + ks) * 32 + lane);
                    mma_bf16(acc, eAh[ks], bv.x, bv.y);
                    mma_bf16(acc, eAh[ks], bv.z, bv.w);
                    mma_bf16(acc, eAl[ks], bv.x, bv.y);
                }
                int jp = nt * 4 + tq;
                int r0 = mt * 16 + g;
                unsigned h01, l01, h23, l23;
                splitpack(fmaxf(acc[0], 0.f), fmaxf(acc[1], 0.f), h01, l01);
                splitpack(fmaxf(acc[2], 0.f), fmaxf(acc[3], 0.f), h23, l23);
                smu[SH2H + r0 * 36 + jp] = h01;
                smu[SH2L + r0 * 36 + jp] = l01;
                smu[SH2H + (r0 + 8) * 36 + jp] = h23;
                smu[SH2L + (r0 + 8) * 36 + jp] = l23;
            }
        }
    }
    __syncthreads();

    // ---- phase B: rw GEMM (split bf16, single-acc chains, pipelined) + fused contraction ----
    {
        int ig = w % 3, eq = w / 3;           // warp = (i-group, edge-quarter)
        int i0 = ig * 8 + 2 * tq;

        unsigned Ah[2][4][4], Al[2][4][4];
#pragma unroll
        for (int mt = 0; mt < 2; mt++) {
            int r0 = (eq * 2 + mt) * 16 + g;
#pragma unroll
            for (int ks = 0; ks < 4; ks++) {
                Ah[mt][ks][0] = smu[SH2H + r0 * 36 + ks * 8 + tq];
                Ah[mt][ks][1] = smu[SH2H + (r0 + 8) * 36 + ks * 8 + tq];
                Ah[mt][ks][2] = smu[SH2H + r0 * 36 + ks * 8 + 4 + tq];
                Ah[mt][ks][3] = smu[SH2H + (r0 + 8) * 36 + ks * 8 + 4 + tq];
                Al[mt][ks][0] = smu[SH2L + r0 * 36 + ks * 8 + tq];
                Al[mt][ks][1] = smu[SH2L + (r0 + 8) * 36 + ks * 8 + tq];
                Al[mt][ks][2] = smu[SH2L + r0 * 36 + ks * 8 + 4 + tq];
                Al[mt][ks][3] = smu[SH2L + (r0 + 8) * 36 + ks * 8 + 4 + tq];
            }
        }

        unsigned long long cp[2][8];
#pragma unroll
        for (int mt = 0; mt < 2; mt++)
#pragma unroll
            for (int x = 0; x < 8; x++) cp[mt][x] = 0ull;

        const uint4* wp = w2pG + (ig * 4) * 32 + lane;
        uint4 bv[4];
#pragma unroll
        for (int ks = 0; ks < 4; ks++) bv[ks] = __ldg(wp + ks * 32);
        float bzc0 = sm[SB2 + i0 * 32];
        float bzc1 = sm[SB2 + (i0 + 1) * 32];

#pragma unroll 2
        for (int j = 0; j < 32; j++) {
            int jn = (j < 31) ? j + 1 : 31;
            const uint4* wpn = (j < 31) ? wp + 384 : wp;
            uint4 nbv[4];
#pragma unroll
            for (int ks = 0; ks < 4; ks++) nbv[ks] = __ldg(wpn + ks * 32);
            float bzn0 = sm[SB2 + i0 * 32 + jn];
            float bzn1 = sm[SB2 + (i0 + 1) * 32 + jn];

            float mn[2][4];
#pragma unroll
            for (int mt = 0; mt < 2; mt++) {
                mn[mt][0] = bzc0; mn[mt][1] = bzc1; mn[mt][2] = bzc0; mn[mt][3] = bzc1;
            }
#pragma unroll
            for (int ks = 0; ks < 4; ks++)
#pragma unroll
                for (int mt = 0; mt < 2; mt++) {
                    mma_bf16(mn[mt], Ah[mt][ks], bv[ks].x, bv[ks].y);
                    mma_bf16(mn[mt], Ah[mt][ks], bv[ks].z, bv[ks].w);
                    mma_bf16(mn[mt], Al[mt][ks], bv[ks].x, bv[ks].y);
                }
#pragma unroll
            for (int mt = 0; mt < 2; mt++) {
                int er = (eq * 2 + mt) * 16 + g;
                float4 t0 = *(const float4*)&sm[STMP + er * 132 + j * 4];
                float4 t1 = *(const float4*)&sm[STMP + (er + 8) * 132 + j * 4];
                unsigned long long ta = packf2(t0.x, t0.y), tb = packf2(t0.z, t0.w);
                unsigned long long tc = packf2(t1.x, t1.y), td = packf2(t1.z, t1.w);
                unsigned long long rp;
                rp = packf2(mn[mt][0], mn[mt][0]); ffma2(cp[mt][0], rp, ta); ffma2(cp[mt][1], rp, tb);
                rp = packf2(mn[mt][1], mn[mt][1]); ffma2(cp[mt][2], rp, ta); ffma2(cp[mt][3], rp, tb);
                rp = packf2(mn[mt][2], mn[mt][2]); ffma2(cp[mt][4], rp, tc); ffma2(cp[mt][5], rp, td);
                rp = packf2(mn[mt][3], mn[mt][3]); ffma2(cp[mt][6], rp, tc); ffma2(cp[mt][7], rp, td);
            }
#pragma unroll
            for (int ks = 0; ks < 4; ks++) bv[ks] = nbv[ks];
            bzc0 = bzn0; bzc1 = bzn1;
            wp = wpn;
        }

        // write conv: k,q (ig<2) -> smem; v (ig==2) -> gmem directly
        if (ig < 2) {
#pragma unroll
            for (int mt = 0; mt < 2; mt++) {
                int er = (eq * 2 + mt) * 16 + g;
                float2 a0 = unpackf2(cp[mt][0]), a1 = unpackf2(cp[mt][1]);
                float2 a2 = unpackf2(cp[mt][2]), a3 = unpackf2(cp[mt][3]);
                float2 a4 = unpackf2(cp[mt][4]), a5 = unpackf2(cp[mt][5]);
                float2 a6 = unpackf2(cp[mt][6]), a7 = unpackf2(cp[mt][7]);
                *(float4*)&sm[SCONV + er * 68 + i0 * 4]             = make_float4(a0.x, a0.y, a1.x, a1.y);
                *(float4*)&sm[SCONV + er * 68 + (i0 + 1) * 4]       = make_float4(a2.x, a2.y, a3.x, a3.y);
                *(float4*)&sm[SCONV + (er + 8) * 68 + i0 * 4]       = make_float4(a4.x, a4.y, a5.x, a5.y);
                *(float4*)&sm[SCONV + (er + 8) * 68 + (i0 + 1) * 4] = make_float4(a6.x, a6.y, a7.x, a7.y);
            }
        } else {
#pragma unroll
            for (int mt = 0; mt < 2; mt++) {
                int er = (eq * 2 + mt) * 16 + g;
                int v0 = (i0 - 16) * 4;
                float2 a0 = unpackf2(cp[mt][0]), a1 = unpackf2(cp[mt][1]);
                float2 a2 = unpackf2(cp[mt][2]), a3 = unpackf2(cp[mt][3]);
                float2 a4 = unpackf2(cp[mt][4]), a5 = unpackf2(cp[mt][5]);
                float2 a6 = unpackf2(cp[mt][6]), a7 = unpackf2(cp[mt][7]);
                if (e0 + er < E) {
                    *(float4*)&vG[(size_t)(e0 + er) * 32 + v0]     = make_float4(a0.x, a0.y, a1.x, a1.y);
                    *(float4*)&vG[(size_t)(e0 + er) * 32 + v0 + 4] = make_float4(a2.x, a2.y, a3.x, a3.y);
                }
                if (e0 + er + 8 < E) {
                    *(float4*)&vG[(size_t)(e0 + er + 8) * 32 + v0]     = make_float4(a4.x, a4.y, a5.x, a5.y);
                    *(float4*)&vG[(size_t)(e0 + er + 8) * 32 + v0 + 4] = make_float4(a6.x, a6.y, a7.x, a7.y);
                }
            }
        }
    }
    __syncthreads();

    // ---- phase C: scores ----
    for (int idx = t; idx < 512; idx += 384) {
        int el2 = idx >> 2, hh = idx & 3;
        float sc = 0.0f;
#pragma unroll
        for (int x = 0; x < 8; x++) {
            int m = 2 * hh + (x >> 2), d = x & 3;
            sc += sm[SCONV + el2 * 68 + m * 4 + d] *
                  sm[SCONV + el2 * 68 + (8 + m) * 4 + d];
        }
        sc *= 0.17677669529663687f;          // 32^-0.5
        sc = sc >= 0.0f ? sc : 0.2f * sc;    // LeakyReLU(0.2)
        int ee = e0 + el2;
        if (ee < E) {
            scoresG[ee * 4 + hh] = sc;
            atomicMaxF(&smaxG[dst[ee] * 4 + hh], sc);
        }
    }
}

// ---------------- softmax accumulate ----------------
__global__ void attn_kernel(const int* __restrict__ dst, int E) {
    int idx = blockIdx.x * blockDim.x + threadIdx.x;
    if (idx >= E * 4) return;
    int e = idx >> 2, h = idx & 3;
    int dn = dst[e];
    float ex = expf(scoresG[idx] - smaxG[dn * 4 + h]);
    const float4* vp = (const float4*)(vG + (size_t)e * 32 + h * 8);
    float4 va = vp[0], vb = vp[1];
    float* p = accG + (size_t)dn * 48 + h * 12;
    redAdd4(p,     ex * va.x, ex * va.y, ex * va.z, ex * va.w);
    redAdd4(p + 4, ex * vb.x, ex * vb.y, ex * vb.z, ex * vb.w);
    redAdd4(p + 8, ex, 0.f, 0.f, 0.f);
}

// ---------------- node output ----------------
__global__ void out_kernel(const float* __restrict__ proj_w, float* __restrict__ out, int N) {
    int idx = blockIdx.x * blockDim.x + threadIdx.x;
    if (idx >= N * 4) return;
    int n = idx >> 2, d = idx & 3;
    float den[4];
#pragma unroll
    for (int h = 0; h < 4; h++) den[h] = accG[(size_t)n * 48 + h * 12 + 8];
    float oc[8];
#pragma unroll
    for (int m2 = 0; m2 < 8; m2++) {
        int h = m2 >> 1;
        float dd = den[h];
        float nm = accG[(size_t)n * 48 + h * 12 + (m2 & 1) * 4 + d];
        oc[m2] = dd > 0.0f ? nm / dd : 0.0f;
    }
    int ro = (d == 0) ? 0 : 8;                 // ix2 = [0,1,1,1]
#pragma unroll
    for (int m = 0; m < 8; m++) {
        float r = 0.0f;
#pragma unroll
        for (int m2 = 0; m2 < 8; m2++) r += proj_w[(ro + m) * 8 + m2] * oc[m2];
        out[(size_t)n * 32 + m * 4 + d] = r;
    }
}

// ---------------- launcher ----------------
extern "C" void kernel_launch(void* const* d_in, const int* in_sizes, int n_in,
                              void* d_out, int out_size) {
    const int*   src        = (const int*)d_in[0];
    const int*   dst        = (const int*)d_in[1];
    const float* basis      = (const float*)d_in[2];
    const float* features   = (const float*)d_in[3];
    const float* edge_feats = (const float*)d_in[4];
    const float* w1         = (const float*)d_in[5];
    const float* b1         = (const float*)d_in[6];
    const float* w2         = (const float*)d_in[7];
    const float* b2         = (const float*)d_in[8];
    const float* ln_w       = (const float*)d_in[9];
    const float* ln_b       = (const float*)d_in[10];
    const float* proj_w     = (const float*)d_in[11];
    float* out = (float*)d_out;

    int E = in_sizes[0];
    int N = in_sizes[3] / 32;

    int setup_threads = SETUP_P2 + SETUP_P1 + N * 48 + N;
    setup_kernel<<<(setup_threads + 255) / 256, 256>>>(w2, w1, features, ln_w, ln_b, N);

    size_t smbytes = STOT * sizeof(float);
    cudaFuncSetAttribute(edge_kernel, cudaFuncAttributeMaxDynamicSharedMemorySize, (int)smbytes);
    edge_kernel<<<(E + 127) / 128, 384, smbytes>>>(src, dst, basis, edge_feats, b1, b2, E);

    attn_kernel<<<(E * 4 + 255) / 256, 256>>>(dst, E);
    out_kernel<<<(N * 4 + 255) / 256, 256>>>(proj_w, out, N);
}

// round 12
// speedup vs baseline: 1.1990x; 1.1990x over previous
#include <cuda_runtime.h>
#include <cuda_bf16.h>
#include <math_constants.h>

#define NN 40000
#define NE 320000

// ---------------- scratch (device globals; no allocation allowed) ----------------
__device__ float fG[NN * 32];
__device__ float scoresG[NE * 4];
__device__ float vG[NE * 32];
__device__ float smaxG[NN * 4];
__device__ float accG[NN * 48];   // per (n,h): [0..7]=num, [8]=den, pad
// w2 split bf16, j-major fragment layout: uint4 = (hi_b0, hi_b1, lo_b0, lo_b1)
// ntile t = j*3 + ig (i = ig*8 + g); index = ((t*4 + ks)*32 + lane)
__device__ uint4 w2pG[96 * 4 * 32];
// w1 split bf16 fragment layout: index = ((nt*2 + ks)*32 + lane)
__device__ uint4 w1pG[16 * 32];

__device__ __forceinline__ void atomicMaxF(float* a, float v) {
    if (v == 0.0f) v = 0.0f;
    if (v >= 0.0f) atomicMax((int*)a, __float_as_int(v));
    else           atomicMin((unsigned int*)a, __float_as_uint(v));
}

__device__ __forceinline__ void redAdd4(float* p, float a, float b, float c, float d) {
    asm volatile("red.global.add.v4.f32 [%0], {%1,%2,%3,%4};"
                 :: "l"(p), "f"(a), "f"(b), "f"(c), "f"(d) : "memory");
}

__device__ __forceinline__ void mma_bf16(float* c, const unsigned* a, unsigned b0, unsigned b1) {
    asm volatile("mma.sync.aligned.m16n8k16.row.col.f32.bf16.bf16.f32 "
                 "{%0,%1,%2,%3}, {%4,%5,%6,%7}, {%8,%9}, {%0,%1,%2,%3};\n"
                 : "+f"(c[0]), "+f"(c[1]), "+f"(c[2]), "+f"(c[3])
                 : "r"(a[0]), "r"(a[1]), "r"(a[2]), "r"(a[3]), "r"(b0), "r"(b1));
}

// packed fp32x2 helpers (sm_100a FFMA2 path)
__device__ __forceinline__ unsigned long long packf2(float x, float y) {
    unsigned long long r;
    asm("mov.b64 %0, {%1,%2};" : "=l"(r) : "f"(x), "f"(y));
    return r;
}
__device__ __forceinline__ float2 unpackf2(unsigned long long v) {
    float2 r;
    asm("mov.b64 {%0,%1}, %2;" : "=f"(r.x), "=f"(r.y) : "l"(v));
    return r;
}
__device__ __forceinline__ void ffma2(unsigned long long& d, unsigned long long a, unsigned long long b) {
    asm("fma.rn.f32x2 %0, %1, %2, %0;" : "+l"(d) : "l"(a), "l"(b));
}

__device__ __forceinline__ void splitpack(float a, float b, unsigned& hi, unsigned& lo) {
    __nv_bfloat16 ha = __float2bfloat16_rn(a), hb = __float2bfloat16_rn(b);
    __nv_bfloat16 la = __float2bfloat16_rn(a - __bfloat162float(ha));
    __nv_bfloat16 lb = __float2bfloat16_rn(b - __bfloat162float(hb));
    hi = ((unsigned)__bfloat16_as_ushort(hb) << 16) | (unsigned)__bfloat16_as_ushort(ha);
    lo = ((unsigned)__bfloat16_as_ushort(lb) << 16) | (unsigned)__bfloat16_as_ushort(la);
}

// ---------------- merged setup: prep_w2 | prep_w1 | init | node_ln ----------------
#define SETUP_P2   (768 * 32)              // 24576
#define SETUP_P1   512
__global__ void setup_kernel(const float* __restrict__ w2, const float* __restrict__ w1,
                             const float* __restrict__ features,
                             const float* __restrict__ ln_w, const float* __restrict__ ln_b,
                             int N) {
    int base = blockIdx.x * 256 + threadIdx.x;
    if (base < SETUP_P2) {
        int idx = base;
        int o = idx >> 5, kp = idx & 31;
        unsigned hiu, lou;
        splitpack(w2[o * 64 + 2 * kp], w2[o * 64 + 2 * kp + 1], hiu, lou);
        int i = o >> 5, j = o & 31;
        int tt = j * 3 + (i >> 3);
        int g = i & 7;
        int ks = kp >> 3;
        int tq = kp & 3;
        int half = (kp >> 2) & 1;
        int frag = (tt * 4 + ks) * 32 + g * 4 + tq;
        ((unsigned*)w2pG)[frag * 4 + half]     = hiu;
        ((unsigned*)w2pG)[frag * 4 + 2 + half] = lou;
        return;
    }
    base -= SETUP_P2;
    if (base < SETUP_P1) {
        int idx = base;
        int lane = idx & 31, ksnt = idx >> 5;
        int ks = ksnt & 1, nt = ksnt >> 1;
        int g = lane >> 2, tq = lane & 3;
        int j = nt * 8 + g;
        int k0 = ks * 16 + 2 * tq;
        unsigned h0, l0, h1, l1;
        splitpack(w1[j * 32 + k0],     w1[j * 32 + k0 + 1],     h0, l0);
        splitpack(w1[j * 32 + k0 + 8], w1[j * 32 + k0 + 8 + 1], h1, l1);
        w1pG[(nt * 2 + ks) * 32 + lane] = make_uint4(h0, h1, l0, l1);
        return;
    }
    base -= SETUP_P1;
    if (base < N * 48) {
        if (base < N * 4) smaxG[base] = -CUDART_INF_F;
        accG[base] = 0.0f;
        return;
    }
    base -= N * 48;
    if (base < N) {
        int n = base;
        float f[32];
        const float4* fp = (const float4*)(features + (size_t)n * 32);
#pragma unroll
        for (int q = 0; q < 8; q++) {
            float4 v = fp[q];
            f[q * 4 + 0] = v.x; f[q * 4 + 1] = v.y; f[q * 4 + 2] = v.z; f[q * 4 + 3] = v.w;
        }
        float nf[16];
#pragma unroll
        for (int m = 0; m < 8; m++) {
            nf[2 * m]     = sqrtf(f[m * 4] * f[m * 4]);
            nf[2 * m + 1] = sqrtf(f[m * 4 + 1] * f[m * 4 + 1] +
                                  f[m * 4 + 2] * f[m * 4 + 2] +
                                  f[m * 4 + 3] * f[m * 4 + 3]);
        }
        float ratio[16];
#pragma unroll
        for (int g = 0; g < 2; g++) {
            float mu = 0.0f;
#pragma unroll
            for (int b = 0; b < 8; b++) mu += nf[8 * g + b];
            mu *= 0.125f;
            float var = 0.0f;
#pragma unroll
            for (int b = 0; b < 8; b++) { float d = nf[8 * g + b] - mu; var += d * d; }
            var *= 0.125f;
            float rs = rsqrtf(var + 1e-5f);
#pragma unroll
            for (int b = 0; b < 8; b++) {
                float l = (nf[8 * g + b] - mu) * rs * ln_w[b] + ln_b[b];
                l = fmaxf(l, 0.0f);
                ratio[8 * g + b] = l / (nf[8 * g + b] + 1e-8f);
            }
        }
        float4* op = (float4*)(fG + (size_t)n * 32);
#pragma unroll
        for (int m = 0; m < 8; m++) {
            float4 v;
            v.x = f[m * 4 + 0] * ratio[2 * m];
            v.y = f[m * 4 + 1] * ratio[2 * m + 1];
            v.z = f[m * 4 + 2] * ratio[2 * m + 1];
            v.w = f[m * 4 + 3] * ratio[2 * m + 1];
            op[m] = v;
        }
    }
}

// ---------------- fused per-edge kernel: 64 edges / 192 threads (R10 winner, unchanged) ----------------
// smem layout (float/uint indices)
#define SB2   0       // 768
#define STMP  768     // 64*132 -> 9216
#define SH2H  9216    // 64*36 uints -> 11520
#define SH2L  11520   // -> 13824
#define SSRC  13824   // 64 -> 13888
#define SSTG  13888
#define SEF   (SSTG)          // 64*32
#define SFU   (SSTG + 2048)   // 64*32
#define SBAS  (SSTG + 4096)   // 64*64
#define SCONV (SSTG)          // 64*68 = 4352 (k,q only; staging dead by then)
#define STOT  22080           // 88320 bytes

__global__ __launch_bounds__(192, 2)
void edge_kernel(const int* __restrict__ src, const int* __restrict__ dst,
                 const float* __restrict__ basis, const float* __restrict__ edge_feats,
                 const float* __restrict__ b1, const float* __restrict__ b2, int E) {
    extern __shared__ float sm[];
    unsigned* smu = (unsigned*)sm;
    int t = threadIdx.x;
    int e0 = blockIdx.x * 64;
    int w = t >> 5, lane = t & 31, g = lane >> 2, tq = lane & 3;

    // ---- stage b2, src, then per-edge inputs ----
    if (t < 64) {
        int ee = e0 + t;
        ((int*)&sm[SSRC])[t] = __ldg(src + (ee < E ? ee : E - 1));
    }
    for (int idx = t; idx < 768; idx += 192) sm[SB2 + idx] = b2[idx];
    __syncthreads();

    for (int idx = t; idx < 512; idx += 192) {
        int el = idx >> 3, q = idx & 7;
        int ee = e0 + el; int ec = ee < E ? ee : E - 1;
        *(float4*)&sm[SEF + el * 32 + q * 4] =
            __ldg((const float4*)edge_feats + (size_t)ec * 8 + q);
        int s = ((const int*)&sm[SSRC])[el];
        *(float4*)&sm[SFU + el * 32 + q * 4] = ((const float4*)fG)[(size_t)s * 8 + q];
    }
    for (int idx = t; idx < 1024; idx += 192) {
        int el = idx >> 4, q = idx & 15;
        int ee = e0 + el; int ec = ee < E ? ee : E - 1;
        *(float4*)&sm[SBAS + el * 64 + q * 4] =
            __ldg((const float4*)basis + (size_t)ec * 16 + q);
    }
    __syncthreads();

    // ---- phase A1: tmp = fU x basis (vectorized float4 LDS) ----
    for (int idx = t; idx < 2048; idx += 192) {
        int el = idx >> 5, j = idx & 31;
        int m = j >> 2, pp = j & 3;
        float4 fv = *(const float4*)&sm[SFU + el * 32 + m * 4];
        float4 r0 = *(const float4*)&sm[SBAS + el * 64 + 0 * 16 + pp * 4];
        float4 r1 = *(const float4*)&sm[SBAS + el * 64 + 1 * 16 + pp * 4];
        float4 r2 = *(const float4*)&sm[SBAS + el * 64 + 2 * 16 + pp * 4];
        float4 r3 = *(const float4*)&sm[SBAS + el * 64 + 3 * 16 + pp * 4];
        float o0 = fv.x * r0.x + fv.y * r1.x + fv.z * r2.x + fv.w * r3.x;
        float o1 = fv.x * r0.y + fv.y * r1.y + fv.z * r2.y + fv.w * r3.y;
        float o2 = fv.x * r0.z + fv.y * r1.z + fv.z * r2.z + fv.w * r3.z;
        float o3 = fv.x * r0.w + fv.y * r1.w + fv.z * r2.w + fv.w * r3.w;
        *(float4*)&sm[STMP + el * 132 + j * 4] = make_float4(o0, o1, o2, o3);
    }

    // ---- phase A2: h = relu(ef@w1^T + b1) via split-bf16 MMA ----
    {
        int cur_mt = -1;
        unsigned eAh[2][4], eAl[2][4];
#pragma unroll
        for (int it = 0; it < 6; it++) {
            int p = w + it * 6;                   // (mt, nt) pair index, 32 total
            if (p < 32) {
                int mt = p >> 3, nt = p & 7;
                if (mt != cur_mt) {
                    cur_mt = mt;
#pragma unroll
                    for (int ks = 0; ks < 2; ks++) {
                        float2 x0 = *(const float2*)&sm[SEF + (mt * 16 + g) * 32 + ks * 16 + 2 * tq];
                        float2 x1 = *(const float2*)&sm[SEF + (mt * 16 + g + 8) * 32 + ks * 16 + 2 * tq];
                        float2 x2 = *(const float2*)&sm[SEF + (mt * 16 + g) * 32 + ks * 16 + 8 + 2 * tq];
                        float2 x3 = *(const float2*)&sm[SEF + (mt * 16 + g + 8) * 32 + ks * 16 + 8 + 2 * tq];
                        splitpack(x0.x, x0.y, eAh[ks][0], eAl[ks][0]);
                        splitpack(x1.x, x1.y, eAh[ks][1], eAl[ks][1]);
                        splitpack(x2.x, x2.y, eAh[ks][2], eAl[ks][2]);
                        splitpack(x3.x, x3.y, eAh[ks][3], eAl[ks][3]);
                    }
                }
                float2 bb = __ldg((const float2*)(b1 + nt * 8 + 2 * tq));
                float acc[4] = {bb.x, bb.y, bb.x, bb.y};
#pragma unroll
                for (int ks = 0; ks < 2; ks++) {
                    uint4 bv = __ldg(w1pG + (nt * 2 + ks) * 32 + lane);
                    mma_bf16(acc, eAh[ks], bv.x, bv.y);
                    mma_bf16(acc, eAh[ks], bv.z, bv.w);
                    mma_bf16(acc, eAl[ks], bv.x, bv.y);
                }
                int jp = nt * 4 + tq;
                int r0 = mt * 16 + g;
                unsigned h01, l01, h23, l23;
                splitpack(fmaxf(acc[0], 0.f), fmaxf(acc[1], 0.f), h01, l01);
                splitpack(fmaxf(acc[2], 0.f), fmaxf(acc[3], 0.f), h23, l23);
                smu[SH2H + r0 * 36 + jp] = h01;
                smu[SH2L + r0 * 36 + jp] = l01;
                smu[SH2H + (r0 + 8) * 36 + jp] = h23;
                smu[SH2L + (r0 + 8) * 36 + jp] = l23;
            }
        }
    }
    __syncthreads();

    // ---- phase B: rw GEMM (split bf16, single-acc chains, pipelined) + fused contraction ----
    {
        int ig = w % 3, ehalf = w / 3;
        int i0 = ig * 8 + 2 * tq;

        unsigned Ah[2][4][4], Al[2][4][4];
#pragma unroll
        for (int mt = 0; mt < 2; mt++) {
            int r0 = (ehalf * 2 + mt) * 16 + g;
#pragma unroll
            for (int ks = 0; ks < 4; ks++) {
                Ah[mt][ks][0] = smu[SH2H + r0 * 36 + ks * 8 + tq];
                Ah[mt][ks][1] = smu[SH2H + (r0 + 8) * 36 + ks * 8 + tq];
                Ah[mt][ks][2] = smu[SH2H + r0 * 36 + ks * 8 + 4 + tq];
                Ah[mt][ks][3] = smu[SH2H + (r0 + 8) * 36 + ks * 8 + 4 + tq];
                Al[mt][ks][0] = smu[SH2L + r0 * 36 + ks * 8 + tq];
                Al[mt][ks][1] = smu[SH2L + (r0 + 8) * 36 + ks * 8 + tq];
                Al[mt][ks][2] = smu[SH2L + r0 * 36 + ks * 8 + 4 + tq];
                Al[mt][ks][3] = smu[SH2L + (r0 + 8) * 36 + ks * 8 + 4 + tq];
            }
        }

        unsigned long long cp[2][8];
#pragma unroll
        for (int mt = 0; mt < 2; mt++)
#pragma unroll
            for (int x = 0; x < 8; x++) cp[mt][x] = 0ull;

        // running fragment pointer: advances 3*4*32 uint4 per j
        const uint4* wp = w2pG + (ig * 4) * 32 + lane;
        uint4 bv[4];
#pragma unroll
        for (int ks = 0; ks < 4; ks++) bv[ks] = __ldg(wp + ks * 32);
        float bzc0 = sm[SB2 + i0 * 32];
        float bzc1 = sm[SB2 + (i0 + 1) * 32];

#pragma unroll 2
        for (int j = 0; j < 32; j++) {
            int jn = (j < 31) ? j + 1 : 31;
            const uint4* wpn = (j < 31) ? wp + 384 : wp;
            uint4 nbv[4];
#pragma unroll
            for (int ks = 0; ks < 4; ks++) nbv[ks] = __ldg(wpn + ks * 32);
            float bzn0 = sm[SB2 + i0 * 32 + jn];
            float bzn1 = sm[SB2 + (i0 + 1) * 32 + jn];

            float mn[2][4];
#pragma unroll
            for (int mt = 0; mt < 2; mt++) {
                mn[mt][0] = bzc0; mn[mt][1] = bzc1; mn[mt][2] = bzc0; mn[mt][3] = bzc1;
            }
            // all three split products accumulate into one chain (acc-dep HMMA = rt)
#pragma unroll
            for (int ks = 0; ks < 4; ks++)
#pragma unroll
                for (int mt = 0; mt < 2; mt++) {
                    mma_bf16(mn[mt], Ah[mt][ks], bv[ks].x, bv[ks].y);
                    mma_bf16(mn[mt], Ah[mt][ks], bv[ks].z, bv[ks].w);
                    mma_bf16(mn[mt], Al[mt][ks], bv[ks].x, bv[ks].y);
                }
#pragma unroll
            for (int mt = 0; mt < 2; mt++) {
                int er = (ehalf * 2 + mt) * 16 + g;
                float4 t0 = *(const float4*)&sm[STMP + er * 132 + j * 4];
                float4 t1 = *(const float4*)&sm[STMP + (er + 8) * 132 + j * 4];
                unsigned long long ta = packf2(t0.x, t0.y), tb = packf2(t0.z, t0.w);
                unsigned long long tc = packf2(t1.x, t1.y), td = packf2(t1.z, t1.w);
                unsigned long long rp;
                rp = packf2(mn[mt][0], mn[mt][0]); ffma2(cp[mt][0], rp, ta); ffma2(cp[mt][1], rp, tb);
                rp = packf2(mn[mt][1], mn[mt][1]); ffma2(cp[mt][2], rp, ta); ffma2(cp[mt][3], rp, tb);
                rp = packf2(mn[mt][2], mn[mt][2]); ffma2(cp[mt][4], rp, tc); ffma2(cp[mt][5], rp, td);
                rp = packf2(mn[mt][3], mn[mt][3]); ffma2(cp[mt][6], rp, tc); ffma2(cp[mt][7], rp, td);
            }
#pragma unroll
            for (int ks = 0; ks < 4; ks++) bv[ks] = nbv[ks];
            bzc0 = bzn0; bzc1 = bzn1;
            wp = wpn;
        }

        // write conv: k,q (ig<2) -> smem; v (ig==2) -> gmem directly
        if (ig < 2) {
#pragma unroll
            for (int mt = 0; mt < 2; mt++) {
                int er = (ehalf * 2 + mt) * 16 + g;
                float2 a0 = unpackf2(cp[mt][0]), a1 = unpackf2(cp[mt][1]);
                float2 a2 = unpackf2(cp[mt][2]), a3 = unpackf2(cp[mt][3]);
                float2 a4 = unpackf2(cp[mt][4]), a5 = unpackf2(cp[mt][5]);
                float2 a6 = unpackf2(cp[mt][6]), a7 = unpackf2(cp[mt][7]);
                *(float4*)&sm[SCONV + er * 68 + i0 * 4]            = make_float4(a0.x, a0.y, a1.x, a1.y);
                *(float4*)&sm[SCONV + er * 68 + (i0 + 1) * 4]      = make_float4(a2.x, a2.y, a3.x, a3.y);
                *(float4*)&sm[SCONV + (er + 8) * 68 + i0 * 4]      = make_float4(a4.x, a4.y, a5.x, a5.y);
                *(float4*)&sm[SCONV + (er + 8) * 68 + (i0 + 1) * 4] = make_float4(a6.x, a6.y, a7.x, a7.y);
            }
        } else {
#pragma unroll
            for (int mt = 0; mt < 2; mt++) {
                int er = (ehalf * 2 + mt) * 16 + g;
                int v0 = (i0 - 16) * 4;
                float2 a0 = unpackf2(cp[mt][0]), a1 = unpackf2(cp[mt][1]);
                float2 a2 = unpackf2(cp[mt][2]), a3 = unpackf2(cp[mt][3]);
                float2 a4 = unpackf2(cp[mt][4]), a5 = unpackf2(cp[mt][5]);
                float2 a6 = unpackf2(cp[mt][6]), a7 = unpackf2(cp[mt][7]);
                if (e0 + er < E) {
                    *(float4*)&vG[(size_t)(e0 + er) * 32 + v0]     = make_float4(a0.x, a0.y, a1.x, a1.y);
                    *(float4*)&vG[(size_t)(e0 + er) * 32 + v0 + 4] = make_float4(a2.x, a2.y, a3.x, a3.y);
                }
                if (e0 + er + 8 < E) {
                    *(float4*)&vG[(size_t)(e0 + er + 8) * 32 + v0]     = make_float4(a4.x, a4.y, a5.x, a5.y);
                    *(float4*)&vG[(size_t)(e0 + er + 8) * 32 + v0 + 4] = make_float4(a6.x, a6.y, a7.x, a7.y);
                }
            }
        }
    }
    __syncthreads();

    // ---- phase C: scores ----
    for (int idx = t; idx < 256; idx += 192) {
        int el2 = idx >> 2, hh = idx & 3;
        float sc = 0.0f;
#pragma unroll
        for (int x = 0; x < 8; x++) {
            int m = 2 * hh + (x >> 2), d = x & 3;
            sc += sm[SCONV + el2 * 68 + m * 4 + d] *
                  sm[SCONV + el2 * 68 + (8 + m) * 4 + d];
        }
        sc *= 0.17677669529663687f;          // 32^-0.5
        sc = sc >= 0.0f ? sc : 0.2f * sc;    // LeakyReLU(0.2)
        int ee = e0 + el2;
        if (ee < E) {
            scoresG[ee * 4 + hh] = sc;
            atomicMaxF(&smaxG[dst[ee] * 4 + hh], sc);
        }
    }
}

// ---------------- softmax accumulate ----------------
__global__ void attn_kernel(const int* __restrict__ dst, int E) {
    int idx = blockIdx.x * blockDim.x + threadIdx.x;
    if (idx >= E * 4) return;
    int e = idx >> 2, h = idx & 3;
    int dn = dst[e];
    float ex = expf(scoresG[idx] - smaxG[dn * 4 + h]);
    const float4* vp = (const float4*)(vG + (size_t)e * 32 + h * 8);
    float4 va = vp[0], vb = vp[1];
    float* p = accG + (size_t)dn * 48 + h * 12;
    redAdd4(p,     ex * va.x, ex * va.y, ex * va.z, ex * va.w);
    redAdd4(p + 4, ex * vb.x, ex * vb.y, ex * vb.z, ex * vb.w);
    redAdd4(p + 8, ex, 0.f, 0.f, 0.f);
}

// ---------------- node output (vectorized: 1 thread per node) ----------------
__global__ void out_kernel(const float* __restrict__ proj_w, float* __restrict__ out, int N) {
    int n = blockIdx.x * blockDim.x + threadIdx.x;
    if (n >= N) return;
    const float4* ap = (const float4*)(accG + (size_t)n * 48);
    float oc[8][4];                           // [m2][d]
#pragma unroll
    for (int h = 0; h < 4; h++) {
        float4 n0 = ap[h * 3 + 0];            // num[m2=2h][d]
        float4 n1 = ap[h * 3 + 1];            // num[m2=2h+1][d]
        float dd = ap[h * 3 + 2].x;           // den
        float inv = dd > 0.0f ? 1.0f / dd : 0.0f;
        oc[2 * h][0] = n0.x * inv; oc[2 * h][1] = n0.y * inv;
        oc[2 * h][2] = n0.z * inv; oc[2 * h][3] = n0.w * inv;
        oc[2 * h + 1][0] = n1.x * inv; oc[2 * h + 1][1] = n1.y * inv;
        oc[2 * h + 1][2] = n1.z * inv; oc[2 * h + 1][3] = n1.w * inv;
    }
    float4* op = (float4*)(out + (size_t)n * 32);
#pragma unroll
    for (int m = 0; m < 8; m++) {
        float4 r = make_float4(0.f, 0.f, 0.f, 0.f);
#pragma unroll
        for (int m2 = 0; m2 < 8; m2++) {
            float w0 = __ldg(proj_w + m * 8 + m2);        // ix2: d==0 -> irrep 0
            float w1 = __ldg(proj_w + (8 + m) * 8 + m2);  // d>0  -> irrep 1
            r.x += w0 * oc[m2][0];
            r.y += w1 * oc[m2][1];
            r.z += w1 * oc[m2][2];
            r.w += w1 * oc[m2][3];
        }
        op[m] = r;
    }
}

// ---------------- launcher ----------------
extern "C" void kernel_launch(void* const* d_in, const int* in_sizes, int n_in,
                              void* d_out, int out_size) {
    const int*   src        = (const int*)d_in[0];
    const int*   dst        = (const int*)d_in[1];
    const float* basis      = (const float*)d_in[2];
    const float* features   = (const float*)d_in[3];
    const float* edge_feats = (const float*)d_in[4];
    const float* w1         = (const float*)d_in[5];
    const float* b1         = (const float*)d_in[6];
    const float* w2         = (const float*)d_in[7];
    const float* b2         = (const float*)d_in[8];
    const float* ln_w       = (const float*)d_in[9];
    const float* ln_b       = (const float*)d_in[10];
    const float* proj_w     = (const float*)d_in[11];
    float* out = (float*)d_out;

    int E = in_sizes[0];
    int N = in_sizes[3] / 32;

    int setup_threads = SETUP_P2 + SETUP_P1 + N * 48 + N;
    setup_kernel<<<(setup_threads + 255) / 256, 256>>>(w2, w1, features, ln_w, ln_b, N);

    size_t smbytes = STOT * sizeof(float);
    cudaFuncSetAttribute(edge_kernel, cudaFuncAttributeMaxDynamicSharedMemorySize, (int)smbytes);
    edge_kernel<<<(E + 63) / 64, 192, smbytes>>>(src, dst, basis, edge_feats, b1, b2, E);

    attn_kernel<<<(E * 4 + 255) / 256, 256>>>(dst, E);
    out_kernel<<<(N + 255) / 256, 256>>>(proj_w, out, N);
}

// round 13
// speedup vs baseline: 1.2221x; 1.0192x over previous
#include <cuda_runtime.h>
#include <cuda_bf16.h>
#include <math_constants.h>

#define NN 40000
#define NE 320000

// ---------------- scratch (device globals; zero-initialized at load) ----------------
// Invariant maintained across launches: accG == 0, smaxG == 0 on entry.
// (smax uses a 0 floor: softmax is shift-invariant for any M >= max, and
//  out_kernel restores both after consuming them.)
__device__ float fG[NN * 32];
__device__ float scoresG[NE * 4];
__device__ float vG[NE * 32];
__device__ float smaxG[NN * 4];
__device__ float accG[NN * 48];   // per (n,h): [0..7]=num, [8]=den, pad
// w2 split bf16, j-major fragment layout: uint4 = (hi_b0, hi_b1, lo_b0, lo_b1)
// ntile t = j*3 + ig (i = ig*8 + g); index = ((t*4 + ks)*32 + lane)
__device__ uint4 w2pG[96 * 4 * 32];
// w1 split bf16 fragment layout: index = ((nt*2 + ks)*32 + lane)
__device__ uint4 w1pG[16 * 32];

// valid when stored value is always >= +0 (sign bit clear), which the 0-floor guarantees
__device__ __forceinline__ void atomicMaxF(float* a, float v) {
    if (v == 0.0f) v = 0.0f;
    if (v >= 0.0f) atomicMax((int*)a, __float_as_int(v));
    else           atomicMin((unsigned int*)a, __float_as_uint(v));
}

__device__ __forceinline__ void redAdd4(float* p, float a, float b, float c, float d) {
    asm volatile("red.global.add.v4.f32 [%0], {%1,%2,%3,%4};"
                 :: "l"(p), "f"(a), "f"(b), "f"(c), "f"(d) : "memory");
}

__device__ __forceinline__ void mma_bf16(float* c, const unsigned* a, unsigned b0, unsigned b1) {
    asm volatile("mma.sync.aligned.m16n8k16.row.col.f32.bf16.bf16.f32 "
                 "{%0,%1,%2,%3}, {%4,%5,%6,%7}, {%8,%9}, {%0,%1,%2,%3};\n"
                 : "+f"(c[0]), "+f"(c[1]), "+f"(c[2]), "+f"(c[3])
                 : "r"(a[0]), "r"(a[1]), "r"(a[2]), "r"(a[3]), "r"(b0), "r"(b1));
}

// packed fp32x2 helpers (sm_100a FFMA2 path)
__device__ __forceinline__ unsigned long long packf2(float x, float y) {
    unsigned long long r;
    asm("mov.b64 %0, {%1,%2};" : "=l"(r) : "f"(x), "f"(y));
    return r;
}
__device__ __forceinline__ float2 unpackf2(unsigned long long v) {
    float2 r;
    asm("mov.b64 {%0,%1}, %2;" : "=f"(r.x), "=f"(r.y) : "l"(v));
    return r;
}
__device__ __forceinline__ void ffma2(unsigned long long& d, unsigned long long a, unsigned long long b) {
    asm("fma.rn.f32x2 %0, %1, %2, %0;" : "+l"(d) : "l"(a), "l"(b));
}

__device__ __forceinline__ void splitpack(float a, float b, unsigned& hi, unsigned& lo) {
    __nv_bfloat16 ha = __float2bfloat16_rn(a), hb = __float2bfloat16_rn(b);
    __nv_bfloat16 la = __float2bfloat16_rn(a - __bfloat162float(ha));
    __nv_bfloat16 lb = __float2bfloat16_rn(b - __bfloat162float(hb));
    hi = ((unsigned)__bfloat16_as_ushort(hb) << 16) | (unsigned)__bfloat16_as_ushort(ha);
    lo = ((unsigned)__bfloat16_as_ushort(lb) << 16) | (unsigned)__bfloat16_as_ushort(la);
}

// ---------------- merged setup: prep_w2 | prep_w1 | node_ln (no init pass) ----------------
#define SETUP_P2   (768 * 32)              // 24576
#define SETUP_P1   512
__global__ void setup_kernel(const float* __restrict__ w2, const float* __restrict__ w1,
                             const float* __restrict__ features,
                             const float* __restrict__ ln_w, const float* __restrict__ ln_b,
                             int N) {
    int base = blockIdx.x * 256 + threadIdx.x;
    if (base < SETUP_P2) {
        int idx = base;
        int o = idx >> 5, kp = idx & 31;
        unsigned hiu, lou;
        splitpack(w2[o * 64 + 2 * kp], w2[o * 64 + 2 * kp + 1], hiu, lou);
        int i = o >> 5, j = o & 31;
        int tt = j * 3 + (i >> 3);
        int g = i & 7;
        int ks = kp >> 3;
        int tq = kp & 3;
        int half = (kp >> 2) & 1;
        int frag = (tt * 4 + ks) * 32 + g * 4 + tq;
        ((unsigned*)w2pG)[frag * 4 + half]     = hiu;
        ((unsigned*)w2pG)[frag * 4 + 2 + half] = lou;
        return;
    }
    base -= SETUP_P2;
    if (base < SETUP_P1) {
        int idx = base;
        int lane = idx & 31, ksnt = idx >> 5;
        int ks = ksnt & 1, nt = ksnt >> 1;
        int g = lane >> 2, tq = lane & 3;
        int j = nt * 8 + g;
        int k0 = ks * 16 + 2 * tq;
        unsigned h0, l0, h1, l1;
        splitpack(w1[j * 32 + k0],     w1[j * 32 + k0 + 1],     h0, l0);
        splitpack(w1[j * 32 + k0 + 8], w1[j * 32 + k0 + 8 + 1], h1, l1);
        w1pG[(nt * 2 + ks) * 32 + lane] = make_uint4(h0, h1, l0, l1);
        return;
    }
    base -= SETUP_P1;
    if (base < N) {
        int n = base;
        float f[32];
        const float4* fp = (const float4*)(features + (size_t)n * 32);
#pragma unroll
        for (int q = 0; q < 8; q++) {
            float4 v = fp[q];
            f[q * 4 + 0] = v.x; f[q * 4 + 1] = v.y; f[q * 4 + 2] = v.z; f[q * 4 + 3] = v.w;
        }
        float nf[16];
#pragma unroll
        for (int m = 0; m < 8; m++) {
            nf[2 * m]     = sqrtf(f[m * 4] * f[m * 4]);
            nf[2 * m + 1] = sqrtf(f[m * 4 + 1] * f[m * 4 + 1] +
                                  f[m * 4 + 2] * f[m * 4 + 2] +
                                  f[m * 4 + 3] * f[m * 4 + 3]);
        }
        float ratio[16];
#pragma unroll
        for (int g = 0; g < 2; g++) {
            float mu = 0.0f;
#pragma unroll
            for (int b = 0; b < 8; b++) mu += nf[8 * g + b];
            mu *= 0.125f;
            float var = 0.0f;
#pragma unroll
            for (int b = 0; b < 8; b++) { float d = nf[8 * g + b] - mu; var += d * d; }
            var *= 0.125f;
            float rs = rsqrtf(var + 1e-5f);
#pragma unroll
            for (int b = 0; b < 8; b++) {
                float l = (nf[8 * g + b] - mu) * rs * ln_w[b] + ln_b[b];
                l = fmaxf(l, 0.0f);
                ratio[8 * g + b] = l / (nf[8 * g + b] + 1e-8f);
            }
        }
        float4* op = (float4*)(fG + (size_t)n * 32);
#pragma unroll
        for (int m = 0; m < 8; m++) {
            float4 v;
            v.x = f[m * 4 + 0] * ratio[2 * m];
            v.y = f[m * 4 + 1] * ratio[2 * m + 1];
            v.z = f[m * 4 + 2] * ratio[2 * m + 1];
            v.w = f[m * 4 + 3] * ratio[2 * m + 1];
            op[m] = v;
        }
    }
}

// ---------------- fused per-edge kernel: 64 edges / 192 threads (R10 winner, unchanged) ----------------
// smem layout (float/uint indices)
#define SB2   0       // 768
#define STMP  768     // 64*132 -> 9216
#define SH2H  9216    // 64*36 uints -> 11520
#define SH2L  11520   // -> 13824
#define SSRC  13824   // 64 -> 13888
#define SSTG  13888
#define SEF   (SSTG)          // 64*32
#define SFU   (SSTG + 2048)   // 64*32
#define SBAS  (SSTG + 4096)   // 64*64
#define SCONV (SSTG)          // 64*68 = 4352 (k,q only; staging dead by then)
#define STOT  22080           // 88320 bytes

__global__ __launch_bounds__(192, 2)
void edge_kernel(const int* __restrict__ src, const int* __restrict__ dst,
                 const float* __restrict__ basis, const float* __restrict__ edge_feats,
                 const float* __restrict__ b1, const float* __restrict__ b2, int E) {
    extern __shared__ float sm[];
    unsigned* smu = (unsigned*)sm;
    int t = threadIdx.x;
    int e0 = blockIdx.x * 64;
    int w = t >> 5, lane = t & 31, g = lane >> 2, tq = lane & 3;

    // ---- stage b2, src, then per-edge inputs ----
    if (t < 64) {
        int ee = e0 + t;
        ((int*)&sm[SSRC])[t] = __ldg(src + (ee < E ? ee : E - 1));
    }
    for (int idx = t; idx < 768; idx += 192) sm[SB2 + idx] = b2[idx];
    __syncthreads();

    for (int idx = t; idx < 512; idx += 192) {
        int el = idx >> 3, q = idx & 7;
        int ee = e0 + el; int ec = ee < E ? ee : E - 1;
        *(float4*)&sm[SEF + el * 32 + q * 4] =
            __ldg((const float4*)edge_feats + (size_t)ec * 8 + q);
        int s = ((const int*)&sm[SSRC])[el];
        *(float4*)&sm[SFU + el * 32 + q * 4] = ((const float4*)fG)[(size_t)s * 8 + q];
    }
    for (int idx = t; idx < 1024; idx += 192) {
        int el = idx >> 4, q = idx & 15;
        int ee = e0 + el; int ec = ee < E ? ee : E - 1;
        *(float4*)&sm[SBAS + el * 64 + q * 4] =
            __ldg((const float4*)basis + (size_t)ec * 16 + q);
    }
    __syncthreads();

    // ---- phase A1: tmp = fU x basis (vectorized float4 LDS) ----
    for (int idx = t; idx < 2048; idx += 192) {
        int el = idx >> 5, j = idx & 31;
        int m = j >> 2, pp = j & 3;
        float4 fv = *(const float4*)&sm[SFU + el * 32 + m * 4];
        float4 r0 = *(const float4*)&sm[SBAS + el * 64 + 0 * 16 + pp * 4];
        float4 r1 = *(const float4*)&sm[SBAS + el * 64 + 1 * 16 + pp * 4];
        float4 r2 = *(const float4*)&sm[SBAS + el * 64 + 2 * 16 + pp * 4];
        float4 r3 = *(const float4*)&sm[SBAS + el * 64 + 3 * 16 + pp * 4];
        float o0 = fv.x * r0.x + fv.y * r1.x + fv.z * r2.x + fv.w * r3.x;
        float o1 = fv.x * r0.y + fv.y * r1.y + fv.z * r2.y + fv.w * r3.y;
        float o2 = fv.x * r0.z + fv.y * r1.z + fv.z * r2.z + fv.w * r3.z;
        float o3 = fv.x * r0.w + fv.y * r1.w + fv.z * r2.w + fv.w * r3.w;
        *(float4*)&sm[STMP + el * 132 + j * 4] = make_float4(o0, o1, o2, o3);
    }

    // ---- phase A2: h = relu(ef@w1^T + b1) via split-bf16 MMA ----
    {
        int cur_mt = -1;
        unsigned eAh[2][4], eAl[2][4];
#pragma unroll
        for (int it = 0; it < 6; it++) {
            int p = w + it * 6;                   // (mt, nt) pair index, 32 total
            if (p < 32) {
                int mt = p >> 3, nt = p & 7;
                if (mt != cur_mt) {
                    cur_mt = mt;
#pragma unroll
                    for (int ks = 0; ks < 2; ks++) {
                        float2 x0 = *(const float2*)&sm[SEF + (mt * 16 + g) * 32 + ks * 16 + 2 * tq];
                        float2 x1 = *(const float2*)&sm[SEF + (mt * 16 + g + 8) * 32 + ks * 16 + 2 * tq];
                        float2 x2 = *(const float2*)&sm[SEF + (mt * 16 + g) * 32 + ks * 16 + 8 + 2 * tq];
                        float2 x3 = *(const float2*)&sm[SEF + (mt * 16 + g + 8) * 32 + ks * 16 + 8 + 2 * tq];
                        splitpack(x0.x, x0.y, eAh[ks][0], eAl[ks][0]);
                        splitpack(x1.x, x1.y, eAh[ks][1], eAl[ks][1]);
                        splitpack(x2.x, x2.y, eAh[ks][2], eAl[ks][2]);
                        splitpack(x3.x, x3.y, eAh[ks][3], eAl[ks][3]);
                    }
                }
                float2 bb = __ldg((const float2*)(b1 + nt * 8 + 2 * tq));
                float acc[4] = {bb.x, bb.y, bb.x, bb.y};
#pragma unroll
                for (int ks = 0; ks < 2; ks++) {
                    uint4 bv = __ldg(w1pG + (nt * 2 + ks) * 32 + lane);
                    mma_bf16(acc, eAh[ks], bv.x, bv.y);
                    mma_bf16(acc, eAh[ks], bv.z, bv.w);
                    mma_bf16(acc, eAl[ks], bv.x, bv.y);
                }
                int jp = nt * 4 + tq;
                int r0 = mt * 16 + g;
                unsigned h01, l01, h23, l23;
                splitpack(fmaxf(acc[0], 0.f), fmaxf(acc[1], 0.f), h01, l01);
                splitpack(fmaxf(acc[2], 0.f), fmaxf(acc[3], 0.f), h23, l23);
                smu[SH2H + r0 * 36 + jp] = h01;
                smu[SH2L + r0 * 36 + jp] = l01;
                smu[SH2H + (r0 + 8) * 36 + jp] = h23;
                smu[SH2L + (r0 + 8) * 36 + jp] = l23;
            }
        }
    }
    __syncthreads();

    // ---- phase B: rw GEMM (split bf16, single-acc chains, pipelined) + fused contraction ----
    {
        int ig = w % 3, ehalf = w / 3;
        int i0 = ig * 8 + 2 * tq;

        unsigned Ah[2][4][4], Al[2][4][4];
#pragma unroll
        for (int mt = 0; mt < 2; mt++) {
            int r0 = (ehalf * 2 + mt) * 16 + g;
#pragma unroll
            for (int ks = 0; ks < 4; ks++) {
                Ah[mt][ks][0] = smu[SH2H + r0 * 36 + ks * 8 + tq];
                Ah[mt][ks][1] = smu[SH2H + (r0 + 8) * 36 + ks * 8 + tq];
                Ah[mt][ks][2] = smu[SH2H + r0 * 36 + ks * 8 + 4 + tq];
                Ah[mt][ks][3] = smu[SH2H + (r0 + 8) * 36 + ks * 8 + 4 + tq];
                Al[mt][ks][0] = smu[SH2L + r0 * 36 + ks * 8 + tq];
                Al[mt][ks][1] = smu[SH2L + (r0 + 8) * 36 + ks * 8 + tq];
                Al[mt][ks][2] = smu[SH2L + r0 * 36 + ks * 8 + 4 + tq];
                Al[mt][ks][3] = smu[SH2L + (r0 + 8) * 36 + ks * 8 + 4 + tq];
            }
        }

        unsigned long long cp[2][8];
#pragma unroll
        for (int mt = 0; mt < 2; mt++)
#pragma unroll
            for (int x = 0; x < 8; x++) cp[mt][x] = 0ull;

        // running fragment pointer: advances 3*4*32 uint4 per j
        const uint4* wp = w2pG + (ig * 4) * 32 + lane;
        uint4 bv[4];
#pragma unroll
        for (int ks = 0; ks < 4; ks++) bv[ks] = __ldg(wp + ks * 32);
        float bzc0 = sm[SB2 + i0 * 32];
        float bzc1 = sm[SB2 + (i0 + 1) * 32];

#pragma unroll 2
        for (int j = 0; j < 32; j++) {
            int jn = (j < 31) ? j + 1 : 31;
            const uint4* wpn = (j < 31) ? wp + 384 : wp;
            uint4 nbv[4];
#pragma unroll
            for (int ks = 0; ks < 4; ks++) nbv[ks] = __ldg(wpn + ks * 32);
            float bzn0 = sm[SB2 + i0 * 32 + jn];
            float bzn1 = sm[SB2 + (i0 + 1) * 32 + jn];

            float mn[2][4];
#pragma unroll
            for (int mt = 0; mt < 2; mt++) {
                mn[mt][0] = bzc0; mn[mt][1] = bzc1; mn[mt][2] = bzc0; mn[mt][3] = bzc1;
            }
            // all three split products accumulate into one chain (acc-dep HMMA = rt)
#pragma unroll
            for (int ks = 0; ks < 4; ks++)
#pragma unroll
                for (int mt = 0; mt < 2; mt++) {
                    mma_bf16(mn[mt], Ah[mt][ks], bv[ks].x, bv[ks].y);
                    mma_bf16(mn[mt], Ah[mt][ks], bv[ks].z, bv[ks].w);
                    mma_bf16(mn[mt], Al[mt][ks], bv[ks].x, bv[ks].y);
                }
#pragma unroll
            for (int mt = 0; mt < 2; mt++) {
                int er = (ehalf * 2 + mt) * 16 + g;
                float4 t0 = *(const float4*)&sm[STMP + er * 132 + j * 4];
                float4 t1 = *(const float4*)&sm[STMP + (er + 8) * 132 + j * 4];
                unsigned long long ta = packf2(t0.x, t0.y), tb = packf2(t0.z, t0.w);
                unsigned long long tc = packf2(t1.x, t1.y), td = packf2(t1.z, t1.w);
                unsigned long long rp;
                rp = packf2(mn[mt][0], mn[mt][0]); ffma2(cp[mt][0], rp, ta); ffma2(cp[mt][1], rp, tb);
                rp = packf2(mn[mt][1], mn[mt][1]); ffma2(cp[mt][2], rp, ta); ffma2(cp[mt][3], rp, tb);
                rp = packf2(mn[mt][2], mn[mt][2]); ffma2(cp[mt][4], rp, tc); ffma2(cp[mt][5], rp, td);
                rp = packf2(mn[mt][3], mn[mt][3]); ffma2(cp[mt][6], rp, tc); ffma2(cp[mt][7], rp, td);
            }
#pragma unroll
            for (int ks = 0; ks < 4; ks++) bv[ks] = nbv[ks];
            bzc0 = bzn0; bzc1 = bzn1;
            wp = wpn;
        }

        // write conv: k,q (ig<2) -> smem; v (ig==2) -> gmem directly
        if (ig < 2) {
#pragma unroll
            for (int mt = 0; mt < 2; mt++) {
                int er = (ehalf * 2 + mt) * 16 + g;
                float2 a0 = unpackf2(cp[mt][0]), a1 = unpackf2(cp[mt][1]);
                float2 a2 = unpackf2(cp[mt][2]), a3 = unpackf2(cp[mt][3]);
                float2 a4 = unpackf2(cp[mt][4]), a5 = unpackf2(cp[mt][5]);
                float2 a6 = unpackf2(cp[mt][6]), a7 = unpackf2(cp[mt][7]);
                *(float4*)&sm[SCONV + er * 68 + i0 * 4]            = make_float4(a0.x, a0.y, a1.x, a1.y);
                *(float4*)&sm[SCONV + er * 68 + (i0 + 1) * 4]      = make_float4(a2.x, a2.y, a3.x, a3.y);
                *(float4*)&sm[SCONV + (er + 8) * 68 + i0 * 4]      = make_float4(a4.x, a4.y, a5.x, a5.y);
                *(float4*)&sm[SCONV + (er + 8) * 68 + (i0 + 1) * 4] = make_float4(a6.x, a6.y, a7.x, a7.y);
            }
        } else {
#pragma unroll
            for (int mt = 0; mt < 2; mt++) {
                int er = (ehalf * 2 + mt) * 16 + g;
                int v0 = (i0 - 16) * 4;
                float2 a0 = unpackf2(cp[mt][0]), a1 = unpackf2(cp[mt][1]);
                float2 a2 = unpackf2(cp[mt][2]), a3 = unpackf2(cp[mt][3]);
                float2 a4 = unpackf2(cp[mt][4]), a5 = unpackf2(cp[mt][5]);
                float2 a6 = unpackf2(cp[mt][6]), a7 = unpackf2(cp[mt][7]);
                if (e0 + er < E) {
                    *(float4*)&vG[(size_t)(e0 + er) * 32 + v0]     = make_float4(a0.x, a0.y, a1.x, a1.y);
                    *(float4*)&vG[(size_t)(e0 + er) * 32 + v0 + 4] = make_float4(a2.x, a2.y, a3.x, a3.y);
                }
                if (e0 + er + 8 < E) {
                    *(float4*)&vG[(size_t)(e0 + er + 8) * 32 + v0]     = make_float4(a4.x, a4.y, a5.x, a5.y);
                    *(float4*)&vG[(size_t)(e0 + er + 8) * 32 + v0 + 4] = make_float4(a6.x, a6.y, a7.x, a7.y);
                }
            }
        }
    }
    __syncthreads();

    // ---- phase C: scores (max floored at 0 via smaxG invariant) ----
    for (int idx = t; idx < 256; idx += 192) {
        int el2 = idx >> 2, hh = idx & 3;
        float sc = 0.0f;
#pragma unroll
        for (int x = 0; x < 8; x++) {
            int m = 2 * hh + (x >> 2), d = x & 3;
            sc += sm[SCONV + el2 * 68 + m * 4 + d] *
                  sm[SCONV + el2 * 68 + (8 + m) * 4 + d];
        }
        sc *= 0.17677669529663687f;          // 32^-0.5
        sc = sc >= 0.0f ? sc : 0.2f * sc;    // LeakyReLU(0.2)
        int ee = e0 + el2;
        if (ee < E) {
            scoresG[ee * 4 + hh] = sc;
            atomicMaxF(&smaxG[dst[ee] * 4 + hh], sc);
        }
    }
}

// ---------------- softmax accumulate ----------------
__global__ void attn_kernel(const int* __restrict__ dst, int E) {
    int idx = blockIdx.x * blockDim.x + threadIdx.x;
    if (idx >= E * 4) return;
    int e = idx >> 2, h = idx & 3;
    int dn = dst[e];
    float ex = expf(scoresG[idx] - smaxG[dn * 4 + h]);
    const float4* vp = (const float4*)(vG + (size_t)e * 32 + h * 8);
    float4 va = vp[0], vb = vp[1];
    float* p = accG + (size_t)dn * 48 + h * 12;
    redAdd4(p,     ex * va.x, ex * va.y, ex * va.z, ex * va.w);
    redAdd4(p + 4, ex * vb.x, ex * vb.y, ex * vb.z, ex * vb.w);
    redAdd4(p + 8, ex, 0.f, 0.f, 0.f);
}

// ---------------- node output + scratch restoration ----------------
__global__ void out_kernel(const float* __restrict__ proj_w, float* __restrict__ out, int N) {
    int idx = blockIdx.x * blockDim.x + threadIdx.x;
    if (idx >= N * 4) return;
    int n = idx >> 2, d = idx & 3;
    float den[4];
#pragma unroll
    for (int h = 0; h < 4; h++) den[h] = accG[(size_t)n * 48 + h * 12 + 8];
    float oc[8];
#pragma unroll
    for (int m2 = 0; m2 < 8; m2++) {
        int h = m2 >> 1;
        float dd = den[h];
        float nm = accG[(size_t)n * 48 + h * 12 + (m2 & 1) * 4 + d];
        oc[m2] = dd > 0.0f ? nm / dd : 0.0f;
    }
    int ro = (d == 0) ? 0 : 8;                 // ix2 = [0,1,1,1]
#pragma unroll
    for (int m = 0; m < 8; m++) {
        float r = 0.0f;
#pragma unroll
        for (int m2 = 0; m2 < 8; m2++) r += proj_w[(ro + m) * 8 + m2] * oc[m2];
        out[(size_t)n * 32 + m * 4 + d] = r;
    }
    // restore the scratch invariant for the next launch.
    // node n's 4 threads live in one warp; these stores are in program order
    // after all of this warp's accG reads (compiler cannot reorder a store
    // across a possibly-aliasing load).
    float4 z = make_float4(0.f, 0.f, 0.f, 0.f);
    float4* ap = (float4*)(accG + (size_t)n * 48 + d * 12);
    ap[0] = z; ap[1] = z; ap[2] = z;
    smaxG[n * 4 + d] = 0.0f;
}

// ---------------- launcher ----------------
extern "C" void kernel_launch(void* const* d_in, const int* in_sizes, int n_in,
                              void* d_out, int out_size) {
    const int*   src        = (const int*)d_in[0];
    const int*   dst        = (const int*)d_in[1];
    const float* basis      = (const float*)d_in[2];
    const float* features   = (const float*)d_in[3];
    const float* edge_feats = (const float*)d_in[4];
    const float* w1         = (const float*)d_in[5];
    const float* b1         = (const float*)d_in[6];
    const float* w2         = (const float*)d_in[7];
    const float* b2         = (const float*)d_in[8];
    const float* ln_w       = (const float*)d_in[9];
    const float* ln_b       = (const float*)d_in[10];
    const float* proj_w     = (const float*)d_in[11];
    float* out = (float*)d_out;

    int E = in_sizes[0];
    int N = in_sizes[3] / 32;

    int setup_threads = SETUP_P2 + SETUP_P1 + N;
    setup_kernel<<<(setup_threads + 255) / 256, 256>>>(w2, w1, features, ln_w, ln_b, N);

    size_t smbytes = STOT * sizeof(float);
    cudaFuncSetAttribute(edge_kernel, cudaFuncAttributeMaxDynamicSharedMemorySize, (int)smbytes);
    edge_kernel<<<(E + 63) / 64, 192, smbytes>>>(src, dst, basis, edge_feats, b1, b2, E);

    attn_kernel<<<(E * 4 + 255) / 256, 256>>>(dst, E);
    out_kernel<<<(N * 4 + 255) / 256, 256>>>(proj_w, out, N);
}

// round 14
// speedup vs baseline: 1.2266x; 1.0037x over previous
#include <cuda_runtime.h>
#include <cuda_bf16.h>
#include <math_constants.h>

#define NN 40000
#define NE 320000

// ---------------- scratch (device globals; zero-initialized at load) ----------------
// Invariant maintained across launches: accG == 0, smaxG == 0 on entry.
// (smax uses a 0 floor: softmax is shift-invariant for any M >= max, and
//  out_kernel restores both after consuming them.)
__device__ float fG[NN * 32];
__device__ float scoresG[NE * 4];
__device__ float vG[NE * 32];
__device__ float smaxG[NN * 4];
__device__ float accG[NN * 48];   // per (n,h): [0..7]=num, [8]=den, pad
// w2 split bf16, j-major fragment layout: uint4 = (hi_b0, hi_b1, lo_b0, lo_b1)
// ntile t = j*3 + ig (i = ig*8 + g); index = ((t*4 + ks)*32 + lane)
__device__ uint4 w2pG[96 * 4 * 32];
// w1 split bf16 fragment layout: index = ((nt*2 + ks)*32 + lane)
__device__ uint4 w1pG[16 * 32];

// valid when stored value is always >= +0 (sign bit clear), which the 0-floor guarantees
__device__ __forceinline__ void atomicMaxF(float* a, float v) {
    if (v == 0.0f) v = 0.0f;
    if (v >= 0.0f) atomicMax((int*)a, __float_as_int(v));
    else           atomicMin((unsigned int*)a, __float_as_uint(v));
}

__device__ __forceinline__ void redAdd4(float* p, float a, float b, float c, float d) {
    asm volatile("red.global.add.v4.f32 [%0], {%1,%2,%3,%4};"
                 :: "l"(p), "f"(a), "f"(b), "f"(c), "f"(d) : "memory");
}
__device__ __forceinline__ void redAdd1(float* p, float a) {
    asm volatile("red.global.add.f32 [%0], %1;" :: "l"(p), "f"(a) : "memory");
}

__device__ __forceinline__ void mma_bf16(float* c, const unsigned* a, unsigned b0, unsigned b1) {
    asm volatile("mma.sync.aligned.m16n8k16.row.col.f32.bf16.bf16.f32 "
                 "{%0,%1,%2,%3}, {%4,%5,%6,%7}, {%8,%9}, {%0,%1,%2,%3};\n"
                 : "+f"(c[0]), "+f"(c[1]), "+f"(c[2]), "+f"(c[3])
                 : "r"(a[0]), "r"(a[1]), "r"(a[2]), "r"(a[3]), "r"(b0), "r"(b1));
}

// packed fp32x2 helpers (sm_100a FFMA2 path)
__device__ __forceinline__ unsigned long long packf2(float x, float y) {
    unsigned long long r;
    asm("mov.b64 %0, {%1,%2};" : "=l"(r) : "f"(x), "f"(y));
    return r;
}
__device__ __forceinline__ float2 unpackf2(unsigned long long v) {
    float2 r;
    asm("mov.b64 {%0,%1}, %2;" : "=f"(r.x), "=f"(r.y) : "l"(v));
    return r;
}
__device__ __forceinline__ void ffma2(unsigned long long& d, unsigned long long a, unsigned long long b) {
    asm("fma.rn.f32x2 %0, %1, %2, %0;" : "+l"(d) : "l"(a), "l"(b));
}

__device__ __forceinline__ void splitpack(float a, float b, unsigned& hi, unsigned& lo) {
    __nv_bfloat16 ha = __float2bfloat16_rn(a), hb = __float2bfloat16_rn(b);
    __nv_bfloat16 la = __float2bfloat16_rn(a - __bfloat162float(ha));
    __nv_bfloat16 lb = __float2bfloat16_rn(b - __bfloat162float(hb));
    hi = ((unsigned)__bfloat16_as_ushort(hb) << 16) | (unsigned)__bfloat16_as_ushort(ha);
    lo = ((unsigned)__bfloat16_as_ushort(lb) << 16) | (unsigned)__bfloat16_as_ushort(la);
}

// ---------------- merged setup: prep_w2 | prep_w1 | node_ln ----------------
#define SETUP_P2   (768 * 32)              // 24576
#define SETUP_P1   512
__global__ void setup_kernel(const float* __restrict__ w2, const float* __restrict__ w1,
                             const float* __restrict__ features,
                             const float* __restrict__ ln_w, const float* __restrict__ ln_b,
                             int N) {
    int base = blockIdx.x * 256 + threadIdx.x;
    if (base < SETUP_P2) {
        int idx = base;
        int o = idx >> 5, kp = idx & 31;
        unsigned hiu, lou;
        splitpack(w2[o * 64 + 2 * kp], w2[o * 64 + 2 * kp + 1], hiu, lou);
        int i = o >> 5, j = o & 31;
        int tt = j * 3 + (i >> 3);
        int g = i & 7;
        int ks = kp >> 3;
        int tq = kp & 3;
        int half = (kp >> 2) & 1;
        int frag = (tt * 4 + ks) * 32 + g * 4 + tq;
        ((unsigned*)w2pG)[frag * 4 + half]     = hiu;
        ((unsigned*)w2pG)[frag * 4 + 2 + half] = lou;
        return;
    }
    base -= SETUP_P2;
    if (base < SETUP_P1) {
        int idx = base;
        int lane = idx & 31, ksnt = idx >> 5;
        int ks = ksnt & 1, nt = ksnt >> 1;
        int g = lane >> 2, tq = lane & 3;
        int j = nt * 8 + g;
        int k0 = ks * 16 + 2 * tq;
        unsigned h0, l0, h1, l1;
        splitpack(w1[j * 32 + k0],     w1[j * 32 + k0 + 1],     h0, l0);
        splitpack(w1[j * 32 + k0 + 8], w1[j * 32 + k0 + 8 + 1], h1, l1);
        w1pG[(nt * 2 + ks) * 32 + lane] = make_uint4(h0, h1, l0, l1);
        return;
    }
    base -= SETUP_P1;
    if (base < N) {
        int n = base;
        float f[32];
        const float4* fp = (const float4*)(features + (size_t)n * 32);
#pragma unroll
        for (int q = 0; q < 8; q++) {
            float4 v = fp[q];
            f[q * 4 + 0] = v.x; f[q * 4 + 1] = v.y; f[q * 4 + 2] = v.z; f[q * 4 + 3] = v.w;
        }
        float nf[16];
#pragma unroll
        for (int m = 0; m < 8; m++) {
            nf[2 * m]     = sqrtf(f[m * 4] * f[m * 4]);
            nf[2 * m + 1] = sqrtf(f[m * 4 + 1] * f[m * 4 + 1] +
                                  f[m * 4 + 2] * f[m * 4 + 2] +
                                  f[m * 4 + 3] * f[m * 4 + 3]);
        }
        float ratio[16];
#pragma unroll
        for (int g = 0; g < 2; g++) {
            float mu = 0.0f;
#pragma unroll
            for (int b = 0; b < 8; b++) mu += nf[8 * g + b];
            mu *= 0.125f;
            float var = 0.0f;
#pragma unroll
            for (int b = 0; b < 8; b++) { float d = nf[8 * g + b] - mu; var += d * d; }
            var *= 0.125f;
            float rs = rsqrtf(var + 1e-5f);
#pragma unroll
            for (int b = 0; b < 8; b++) {
                float l = (nf[8 * g + b] - mu) * rs * ln_w[b] + ln_b[b];
                l = fmaxf(l, 0.0f);
                ratio[8 * g + b] = l / (nf[8 * g + b] + 1e-8f);
            }
        }
        float4* op = (float4*)(fG + (size_t)n * 32);
#pragma unroll
        for (int m = 0; m < 8; m++) {
            float4 v;
            v.x = f[m * 4 + 0] * ratio[2 * m];
            v.y = f[m * 4 + 1] * ratio[2 * m + 1];
            v.z = f[m * 4 + 2] * ratio[2 * m + 1];
            v.w = f[m * 4 + 3] * ratio[2 * m + 1];
            op[m] = v;
        }
    }
}

// ---------------- fused per-edge kernel: 64 edges / 192 threads ----------------
// smem layout (float/uint indices)
#define SB2   0       // 768
#define STMP  768     // 64*132 -> 9216
#define SH2H  9216    // 64*36 uints -> 11520
#define SH2L  11520   // -> 13824
#define SSTG  13824
#define SEF   (SSTG)          // 64*32
#define SFU   (SSTG + 2048)   // 64*32
#define SBAS  (SSTG + 4096)   // 64*64
#define SCONV (SSTG)          // 64*68 = 4352 (k,q only; staging dead by then)
#define STOT  22016           // 88064 bytes

__global__ __launch_bounds__(192, 2)
void edge_kernel(const int* __restrict__ src, const int* __restrict__ dst,
                 const float* __restrict__ basis, const float* __restrict__ edge_feats,
                 const float* __restrict__ b1, const float* __restrict__ b2, int E) {
    extern __shared__ float sm[];
    unsigned* smu = (unsigned*)sm;
    int t = threadIdx.x;
    int e0 = blockIdx.x * 64;
    int w = t >> 5, lane = t & 31, g = lane >> 2, tq = lane & 3;

    // ---- stage b2 + per-edge inputs (src loaded directly; L1 broadcast) ----
    for (int idx = t; idx < 768; idx += 192) sm[SB2 + idx] = b2[idx];

    for (int idx = t; idx < 512; idx += 192) {
        int el = idx >> 3, q = idx & 7;
        int ee = e0 + el; int ec = ee < E ? ee : E - 1;
        *(float4*)&sm[SEF + el * 32 + q * 4] =
            __ldg((const float4*)edge_feats + (size_t)ec * 8 + q);
        int s = __ldg(src + ec);
        *(float4*)&sm[SFU + el * 32 + q * 4] = ((const float4*)fG)[(size_t)s * 8 + q];
    }
    for (int idx = t; idx < 1024; idx += 192) {
        int el = idx >> 4, q = idx & 15;
        int ee = e0 + el; int ec = ee < E ? ee : E - 1;
        *(float4*)&sm[SBAS + el * 64 + q * 4] =
            __ldg((const float4*)basis + (size_t)ec * 16 + q);
    }
    __syncthreads();

    // ---- phase A1: tmp = fU x basis (vectorized float4 LDS) ----
    for (int idx = t; idx < 2048; idx += 192) {
        int el = idx >> 5, j = idx & 31;
        int m = j >> 2, pp = j & 3;
        float4 fv = *(const float4*)&sm[SFU + el * 32 + m * 4];
        float4 r0 = *(const float4*)&sm[SBAS + el * 64 + 0 * 16 + pp * 4];
        float4 r1 = *(const float4*)&sm[SBAS + el * 64 + 1 * 16 + pp * 4];
        float4 r2 = *(const float4*)&sm[SBAS + el * 64 + 2 * 16 + pp * 4];
        float4 r3 = *(const float4*)&sm[SBAS + el * 64 + 3 * 16 + pp * 4];
        float o0 = fv.x * r0.x + fv.y * r1.x + fv.z * r2.x + fv.w * r3.x;
        float o1 = fv.x * r0.y + fv.y * r1.y + fv.z * r2.y + fv.w * r3.y;
        float o2 = fv.x * r0.z + fv.y * r1.z + fv.z * r2.z + fv.w * r3.z;
        float o3 = fv.x * r0.w + fv.y * r1.w + fv.z * r2.w + fv.w * r3.w;
        *(float4*)&sm[STMP + el * 132 + j * 4] = make_float4(o0, o1, o2, o3);
    }

    // ---- phase A2: h = relu(ef@w1^T + b1) via split-bf16 MMA ----
    {
        int cur_mt = -1;
        unsigned eAh[2][4], eAl[2][4];
#pragma unroll
        for (int it = 0; it < 6; it++) {
            int p = w + it * 6;                   // (mt, nt) pair index, 32 total
            if (p < 32) {
                int mt = p >> 3, nt = p & 7;
                if (mt != cur_mt) {
                    cur_mt = mt;
#pragma unroll
                    for (int ks = 0; ks < 2; ks++) {
                        float2 x0 = *(const float2*)&sm[SEF + (mt * 16 + g) * 32 + ks * 16 + 2 * tq];
                        float2 x1 = *(const float2*)&sm[SEF + (mt * 16 + g + 8) * 32 + ks * 16 + 2 * tq];
                        float2 x2 = *(const float2*)&sm[SEF + (mt * 16 + g) * 32 + ks * 16 + 8 + 2 * tq];
                        float2 x3 = *(const float2*)&sm[SEF + (mt * 16 + g + 8) * 32 + ks * 16 + 8 + 2 * tq];
                        splitpack(x0.x, x0.y, eAh[ks][0], eAl[ks][0]);
                        splitpack(x1.x, x1.y, eAh[ks][1], eAl[ks][1]);
                        splitpack(x2.x, x2.y, eAh[ks][2], eAl[ks][2]);
                        splitpack(x3.x, x3.y, eAh[ks][3], eAl[ks][3]);
                    }
                }
                float2 bb = __ldg((const float2*)(b1 + nt * 8 + 2 * tq));
                float acc[4] = {bb.x, bb.y, bb.x, bb.y};
#pragma unroll
                for (int ks = 0; ks < 2; ks++) {
                    uint4 bv = __ldg(w1pG + (nt * 2 + ks) * 32 + lane);
                    mma_bf16(acc, eAh[ks], bv.x, bv.y);
                    mma_bf16(acc, eAh[ks], bv.z, bv.w);
                    mma_bf16(acc, eAl[ks], bv.x, bv.y);
                }
                int jp = nt * 4 + tq;
                int r0 = mt * 16 + g;
                unsigned h01, l01, h23, l23;
                splitpack(fmaxf(acc[0], 0.f), fmaxf(acc[1], 0.f), h01, l01);
                splitpack(fmaxf(acc[2], 0.f), fmaxf(acc[3], 0.f), h23, l23);
                smu[SH2H + r0 * 36 + jp] = h01;
                smu[SH2L + r0 * 36 + jp] = l01;
                smu[SH2H + (r0 + 8) * 36 + jp] = h23;
                smu[SH2L + (r0 + 8) * 36 + jp] = l23;
            }
        }
    }
    __syncthreads();

    // ---- phase B: rw GEMM (split bf16, single-acc chains, pipelined) + fused contraction ----
    {
        int ig = w % 3, ehalf = w / 3;
        int i0 = ig * 8 + 2 * tq;

        unsigned Ah[2][4][4], Al[2][4][4];
#pragma unroll
        for (int mt = 0; mt < 2; mt++) {
            int r0 = (ehalf * 2 + mt) * 16 + g;
#pragma unroll
            for (int ks = 0; ks < 4; ks++) {
                Ah[mt][ks][0] = smu[SH2H + r0 * 36 + ks * 8 + tq];
                Ah[mt][ks][1] = smu[SH2H + (r0 + 8) * 36 + ks * 8 + tq];
                Ah[mt][ks][2] = smu[SH2H + r0 * 36 + ks * 8 + 4 + tq];
                Ah[mt][ks][3] = smu[SH2H + (r0 + 8) * 36 + ks * 8 + 4 + tq];
                Al[mt][ks][0] = smu[SH2L + r0 * 36 + ks * 8 + tq];
                Al[mt][ks][1] = smu[SH2L + (r0 + 8) * 36 + ks * 8 + tq];
                Al[mt][ks][2] = smu[SH2L + r0 * 36 + ks * 8 + 4 + tq];
                Al[mt][ks][3] = smu[SH2L + (r0 + 8) * 36 + ks * 8 + 4 + tq];
            }
        }

        unsigned long long cp[2][8];
#pragma unroll
        for (int mt = 0; mt < 2; mt++)
#pragma unroll
            for (int x = 0; x < 8; x++) cp[mt][x] = 0ull;

        // running fragment pointer: advances 3*4*32 uint4 per j
        const uint4* wp = w2pG + (ig * 4) * 32 + lane;
        uint4 bv[4];
#pragma unroll
        for (int ks = 0; ks < 4; ks++) bv[ks] = __ldg(wp + ks * 32);
        float bzc0 = sm[SB2 + i0 * 32];
        float bzc1 = sm[SB2 + (i0 + 1) * 32];

#pragma unroll 2
        for (int j = 0; j < 32; j++) {
            int jn = (j < 31) ? j + 1 : 31;
            const uint4* wpn = (j < 31) ? wp + 384 : wp;
            uint4 nbv[4];
#pragma unroll
            for (int ks = 0; ks < 4; ks++) nbv[ks] = __ldg(wpn + ks * 32);
            float bzn0 = sm[SB2 + i0 * 32 + jn];
            float bzn1 = sm[SB2 + (i0 + 1) * 32 + jn];

            float mn[2][4];
#pragma unroll
            for (int mt = 0; mt < 2; mt++) {
                mn[mt][0] = bzc0; mn[mt][1] = bzc1; mn[mt][2] = bzc0; mn[mt][3] = bzc1;
            }
            // all three split products accumulate into one chain (acc-dep HMMA = rt)
#pragma unroll
            for (int ks = 0; ks < 4; ks++)
#pragma unroll
                for (int mt = 0; mt < 2; mt++) {
                    mma_bf16(mn[mt], Ah[mt][ks], bv[ks].x, bv[ks].y);
                    mma_bf16(mn[mt], Ah[mt][ks], bv[ks].z, bv[ks].w);
                    mma_bf16(mn[mt], Al[mt][ks], bv[ks].x, bv[ks].y);
                }
#pragma unroll
            for (int mt = 0; mt < 2; mt++) {
                int er = (ehalf * 2 + mt) * 16 + g;
                float4 t0 = *(const float4*)&sm[STMP + er * 132 + j * 4];
                float4 t1 = *(const float4*)&sm[STMP + (er + 8) * 132 + j * 4];
                unsigned long long ta = packf2(t0.x, t0.y), tb = packf2(t0.z, t0.w);
                unsigned long long tc = packf2(t1.x, t1.y), td = packf2(t1.z, t1.w);
                unsigned long long rp;
                rp = packf2(mn[mt][0], mn[mt][0]); ffma2(cp[mt][0], rp, ta); ffma2(cp[mt][1], rp, tb);
                rp = packf2(mn[mt][1], mn[mt][1]); ffma2(cp[mt][2], rp, ta); ffma2(cp[mt][3], rp, tb);
                rp = packf2(mn[mt][2], mn[mt][2]); ffma2(cp[mt][4], rp, tc); ffma2(cp[mt][5], rp, td);
                rp = packf2(mn[mt][3], mn[mt][3]); ffma2(cp[mt][6], rp, tc); ffma2(cp[mt][7], rp, td);
            }
#pragma unroll
            for (int ks = 0; ks < 4; ks++) bv[ks] = nbv[ks];
            bzc0 = bzn0; bzc1 = bzn1;
            wp = wpn;
        }

        // write conv: k,q (ig<2) -> smem; v (ig==2) -> gmem directly
        if (ig < 2) {
#pragma unroll
            for (int mt = 0; mt < 2; mt++) {
                int er = (ehalf * 2 + mt) * 16 + g;
                float2 a0 = unpackf2(cp[mt][0]), a1 = unpackf2(cp[mt][1]);
                float2 a2 = unpackf2(cp[mt][2]), a3 = unpackf2(cp[mt][3]);
                float2 a4 = unpackf2(cp[mt][4]), a5 = unpackf2(cp[mt][5]);
                float2 a6 = unpackf2(cp[mt][6]), a7 = unpackf2(cp[mt][7]);
                *(float4*)&sm[SCONV + er * 68 + i0 * 4]            = make_float4(a0.x, a0.y, a1.x, a1.y);
                *(float4*)&sm[SCONV + er * 68 + (i0 + 1) * 4]      = make_float4(a2.x, a2.y, a3.x, a3.y);
                *(float4*)&sm[SCONV + (er + 8) * 68 + i0 * 4]      = make_float4(a4.x, a4.y, a5.x, a5.y);
                *(float4*)&sm[SCONV + (er + 8) * 68 + (i0 + 1) * 4] = make_float4(a6.x, a6.y, a7.x, a7.y);
            }
        } else {
#pragma unroll
            for (int mt = 0; mt < 2; mt++) {
                int er = (ehalf * 2 + mt) * 16 + g;
                int v0 = (i0 - 16) * 4;
                float2 a0 = unpackf2(cp[mt][0]), a1 = unpackf2(cp[mt][1]);
                float2 a2 = unpackf2(cp[mt][2]), a3 = unpackf2(cp[mt][3]);
                float2 a4 = unpackf2(cp[mt][4]), a5 = unpackf2(cp[mt][5]);
                float2 a6 = unpackf2(cp[mt][6]), a7 = unpackf2(cp[mt][7]);
                if (e0 + er < E) {
                    *(float4*)&vG[(size_t)(e0 + er) * 32 + v0]     = make_float4(a0.x, a0.y, a1.x, a1.y);
                    *(float4*)&vG[(size_t)(e0 + er) * 32 + v0 + 4] = make_float4(a2.x, a2.y, a3.x, a3.y);
                }
                if (e0 + er + 8 < E) {
                    *(float4*)&vG[(size_t)(e0 + er + 8) * 32 + v0]     = make_float4(a4.x, a4.y, a5.x, a5.y);
                    *(float4*)&vG[(size_t)(e0 + er + 8) * 32 + v0 + 4] = make_float4(a6.x, a6.y, a7.x, a7.y);
                }
            }
        }
    }
    __syncthreads();

    // ---- phase C: scores (max floored at 0 via smaxG invariant) ----
    for (int idx = t; idx < 256; idx += 192) {
        int el2 = idx >> 2, hh = idx & 3;
        float sc = 0.0f;
#pragma unroll
        for (int x = 0; x < 8; x++) {
            int m = 2 * hh + (x >> 2), d = x & 3;
            sc += sm[SCONV + el2 * 68 + m * 4 + d] *
                  sm[SCONV + el2 * 68 + (8 + m) * 4 + d];
        }
        sc *= 0.17677669529663687f;          // 32^-0.5
        sc = sc >= 0.0f ? sc : 0.2f * sc;    // LeakyReLU(0.2)
        int ee = e0 + el2;
        if (ee < E) {
            scoresG[ee * 4 + hh] = sc;
            atomicMaxF(&smaxG[dst[ee] * 4 + hh], sc);
        }
    }
}

// ---------------- softmax accumulate: one thread per edge ----------------
__global__ void attn_kernel(const int* __restrict__ dst, int E) {
    int e = blockIdx.x * blockDim.x + threadIdx.x;
    if (e >= E) return;
    int dn = __ldg(dst + e);
    float4 sc = *(const float4*)(scoresG + (size_t)e * 4);
    float4 mx = *(const float4*)(smaxG + (size_t)dn * 4);
    float ex[4];
    ex[0] = expf(sc.x - mx.x);
    ex[1] = expf(sc.y - mx.y);
    ex[2] = expf(sc.z - mx.z);
    ex[3] = expf(sc.w - mx.w);
    const float4* vp = (const float4*)(vG + (size_t)e * 32);
    float* pb = accG + (size_t)dn * 48;
#pragma unroll
    for (int h = 0; h < 4; h++) {
        float4 va = vp[h * 2], vb = vp[h * 2 + 1];
        float x = ex[h];
        float* p = pb + h * 12;
        redAdd4(p,     x * va.x, x * va.y, x * va.z, x * va.w);
        redAdd4(p + 4, x * vb.x, x * vb.y, x * vb.z, x * vb.w);
        redAdd1(p + 8, x);
    }
}

// ---------------- node output + scratch restoration ----------------
__global__ void out_kernel(const float* __restrict__ proj_w, float* __restrict__ out, int N) {
    int idx = blockIdx.x * blockDim.x + threadIdx.x;
    if (idx >= N * 4) return;
    int n = idx >> 2, d = idx & 3;
    float den[4];
#pragma unroll
    for (int h = 0; h < 4; h++) den[h] = accG[(size_t)n * 48 + h * 12 + 8];
    float oc[8];
#pragma unroll
    for (int m2 = 0; m2 < 8; m2++) {
        int h = m2 >> 1;
        float dd = den[h];
        float nm = accG[(size_t)n * 48 + h * 12 + (m2 & 1) * 4 + d];
        oc[m2] = dd > 0.0f ? nm / dd : 0.0f;
    }
    int ro = (d == 0) ? 0 : 8;                 // ix2 = [0,1,1,1]
#pragma unroll
    for (int m = 0; m < 8; m++) {
        float r = 0.0f;
#pragma unroll
        for (int m2 = 0; m2 < 8; m2++) r += proj_w[(ro + m) * 8 + m2] * oc[m2];
        out[(size_t)n * 32 + m * 4 + d] = r;
    }
    // restore the scratch invariant for the next launch (program-order after reads)
    float4 z = make_float4(0.f, 0.f, 0.f, 0.f);
    float4* ap = (float4*)(accG + (size_t)n * 48 + d * 12);
    ap[0] = z; ap[1] = z; ap[2] = z;
    smaxG[n * 4 + d] = 0.0f;
}

// ---------------- launcher ----------------
extern "C" void kernel_launch(void* const* d_in, const int* in_sizes, int n_in,
                              void* d_out, int out_size) {
    const int*   src        = (const int*)d_in[0];
    const int*   dst        = (const int*)d_in[1];
    const float* basis      = (const float*)d_in[2];
    const float* features   = (const float*)d_in[3];
    const float* edge_feats = (const float*)d_in[4];
    const float* w1         = (const float*)d_in[5];
    const float* b1         = (const float*)d_in[6];
    const float* w2         = (const float*)d_in[7];
    const float* b2         = (const float*)d_in[8];
    const float* ln_w       = (const float*)d_in[9];
    const float* ln_b       = (const float*)d_in[10];
    const float* proj_w     = (const float*)d_in[11];
    float* out = (float*)d_out;

    int E = in_sizes[0];
    int N = in_sizes[3] / 32;

    int setup_threads = SETUP_P2 + SETUP_P1 + N;
    setup_kernel<<<(setup_threads + 255) / 256, 256>>>(w2, w1, features, ln_w, ln_b, N);

    size_t smbytes = STOT * sizeof(float);
    cudaFuncSetAttribute(edge_kernel, cudaFuncAttributeMaxDynamicSharedMemorySize, (int)smbytes);
    edge_kernel<<<(E + 63) / 64, 192, smbytes>>>(src, dst, basis, edge_feats, b1, b2, E);

    attn_kernel<<<(E + 255) / 256, 256>>>(dst, E);
    out_kernel<<<(N * 4 + 255) / 256, 256>>>(proj_w, out, N);
}

// round 15
// speedup vs baseline: 1.3484x; 1.0993x over previous
#include <cuda_runtime.h>
#include <cuda_bf16.h>
#include <math_constants.h>

#define NN 40000
#define NE 320000

// ---------------- scratch (device globals; zero-initialized at load) ----------------
// Invariant maintained across launches: accG == 0, smaxG == 0 on entry.
__device__ float fG[NN * 32];
__device__ float scoresG[NE * 4];
__device__ float vG[NE * 32];
__device__ float smaxG[NN * 4];
__device__ float accG[NN * 48];   // per (n,h): [0..7]=num, [8]=den, pad
__device__ uint4 w2pG[96 * 4 * 32];
__device__ uint4 w1pG[16 * 32];

// valid when stored value is always >= +0 (sign bit clear), which the 0-floor guarantees
__device__ __forceinline__ void atomicMaxF(float* a, float v) {
    if (v == 0.0f) v = 0.0f;
    if (v >= 0.0f) atomicMax((int*)a, __float_as_int(v));
    else           atomicMin((unsigned int*)a, __float_as_uint(v));
}

__device__ __forceinline__ void redAdd4(float* p, float a, float b, float c, float d) {
    asm volatile("red.global.add.v4.f32 [%0], {%1,%2,%3,%4};"
                 :: "l"(p), "f"(a), "f"(b), "f"(c), "f"(d) : "memory");
}
__device__ __forceinline__ void redAdd1(float* p, float a) {
    asm volatile("red.global.add.f32 [%0], %1;" :: "l"(p), "f"(a) : "memory");
}

__device__ __forceinline__ void cpasync16(unsigned smaddr, const void* g) {
    asm volatile("cp.async.cg.shared.global [%0], [%1], 16;" :: "r"(smaddr), "l"(g) : "memory");
}
__device__ __forceinline__ void cpasync_wait_all() {
    asm volatile("cp.async.commit_group;\ncp.async.wait_group 0;" ::: "memory");
}

__device__ __forceinline__ void mma_bf16(float* c, const unsigned* a, unsigned b0, unsigned b1) {
    asm volatile("mma.sync.aligned.m16n8k16.row.col.f32.bf16.bf16.f32 "
                 "{%0,%1,%2,%3}, {%4,%5,%6,%7}, {%8,%9}, {%0,%1,%2,%3};\n"
                 : "+f"(c[0]), "+f"(c[1]), "+f"(c[2]), "+f"(c[3])
                 : "r"(a[0]), "r"(a[1]), "r"(a[2]), "r"(a[3]), "r"(b0), "r"(b1));
}

// packed fp32x2 helpers (sm_100a FFMA2 path)
__device__ __forceinline__ unsigned long long packf2(float x, float y) {
    unsigned long long r;
    asm("mov.b64 %0, {%1,%2};" : "=l"(r) : "f"(x), "f"(y));
    return r;
}
__device__ __forceinline__ float2 unpackf2(unsigned long long v) {
    float2 r;
    asm("mov.b64 {%0,%1}, %2;" : "=f"(r.x), "=f"(r.y) : "l"(v));
    return r;
}
__device__ __forceinline__ void ffma2(unsigned long long& d, unsigned long long a, unsigned long long b) {
    asm("fma.rn.f32x2 %0, %1, %2, %0;" : "+l"(d) : "l"(a), "l"(b));
}

__device__ __forceinline__ void splitpack(float a, float b, unsigned& hi, unsigned& lo) {
    __nv_bfloat16 ha = __float2bfloat16_rn(a), hb = __float2bfloat16_rn(b);
    __nv_bfloat16 la = __float2bfloat16_rn(a - __bfloat162float(ha));
    __nv_bfloat16 lb = __float2bfloat16_rn(b - __bfloat162float(hb));
    hi = ((unsigned)__bfloat16_as_ushort(hb) << 16) | (unsigned)__bfloat16_as_ushort(ha);
    lo = ((unsigned)__bfloat16_as_ushort(lb) << 16) | (unsigned)__bfloat16_as_ushort(la);
}

// ---------------- merged setup: prep_w2 | prep_w1 | node_ln ----------------
#define SETUP_P2   (768 * 32)              // 24576
#define SETUP_P1   512
__global__ void setup_kernel(const float* __restrict__ w2, const float* __restrict__ w1,
                             const float* __restrict__ features,
                             const float* __restrict__ ln_w, const float* __restrict__ ln_b,
                             int N) {
    int base = blockIdx.x * 256 + threadIdx.x;
    if (base < SETUP_P2) {
        int idx = base;
        int o = idx >> 5, kp = idx & 31;
        unsigned hiu, lou;
        splitpack(w2[o * 64 + 2 * kp], w2[o * 64 + 2 * kp + 1], hiu, lou);
        int i = o >> 5, j = o & 31;
        int tt = j * 3 + (i >> 3);
        int g = i & 7;
        int ks = kp >> 3;
        int tq = kp & 3;
        int half = (kp >> 2) & 1;
        int frag = (tt * 4 + ks) * 32 + g * 4 + tq;
        ((unsigned*)w2pG)[frag * 4 + half]     = hiu;
        ((unsigned*)w2pG)[frag * 4 + 2 + half] = lou;
        return;
    }
    base -= SETUP_P2;
    if (base < SETUP_P1) {
        int idx = base;
        int lane = idx & 31, ksnt = idx >> 5;
        int ks = ksnt & 1, nt = ksnt >> 1;
        int g = lane >> 2, tq = lane & 3;
        int j = nt * 8 + g;
        int k0 = ks * 16 + 2 * tq;
        unsigned h0, l0, h1, l1;
        splitpack(w1[j * 32 + k0],     w1[j * 32 + k0 + 1],     h0, l0);
        splitpack(w1[j * 32 + k0 + 8], w1[j * 32 + k0 + 8 + 1], h1, l1);
        w1pG[(nt * 2 + ks) * 32 + lane] = make_uint4(h0, h1, l0, l1);
        return;
    }
    base -= SETUP_P1;
    if (base < N) {
        int n = base;
        float f[32];
        const float4* fp = (const float4*)(features + (size_t)n * 32);
#pragma unroll
        for (int q = 0; q < 8; q++) {
            float4 v = fp[q];
            f[q * 4 + 0] = v.x; f[q * 4 + 1] = v.y; f[q * 4 + 2] = v.z; f[q * 4 + 3] = v.w;
        }
        float nf[16];
#pragma unroll
        for (int m = 0; m < 8; m++) {
            nf[2 * m]     = sqrtf(f[m * 4] * f[m * 4]);
            nf[2 * m + 1] = sqrtf(f[m * 4 + 1] * f[m * 4 + 1] +
                                  f[m * 4 + 2] * f[m * 4 + 2] +
                                  f[m * 4 + 3] * f[m * 4 + 3]);
        }
        float ratio[16];
#pragma unroll
        for (int g = 0; g < 2; g++) {
            float mu = 0.0f;
#pragma unroll
            for (int b = 0; b < 8; b++) mu += nf[8 * g + b];
            mu *= 0.125f;
            float var = 0.0f;
#pragma unroll
            for (int b = 0; b < 8; b++) { float d = nf[8 * g + b] - mu; var += d * d; }
            var *= 0.125f;
            float rs = rsqrtf(var + 1e-5f);
#pragma unroll
            for (int b = 0; b < 8; b++) {
                float l = (nf[8 * g + b] - mu) * rs * ln_w[b] + ln_b[b];
                l = fmaxf(l, 0.0f);
                ratio[8 * g + b] = l / (nf[8 * g + b] + 1e-8f);
            }
        }
        float4* op = (float4*)(fG + (size_t)n * 32);
#pragma unroll
        for (int m = 0; m < 8; m++) {
            float4 v;
            v.x = f[m * 4 + 0] * ratio[2 * m];
            v.y = f[m * 4 + 1] * ratio[2 * m + 1];
            v.z = f[m * 4 + 2] * ratio[2 * m + 1];
            v.w = f[m * 4 + 3] * ratio[2 * m + 1];
            op[m] = v;
        }
    }
}

// ---------------- fused per-edge kernel: 64 edges / 192 threads ----------------
// smem layout (float/uint indices)
#define SB2   0       // 768
#define STMP  768     // 64*132 -> 9216
#define SH2H  9216    // 64*36 uints -> 11520
#define SH2L  11520   // -> 13824
#define SSTG  13824
#define SEF   (SSTG)          // 64*32
#define SFU   (SSTG + 2048)   // 64*32
#define SBAS  (SSTG + 4096)   // 64*64
#define SCONV (SSTG)          // 64*68 = 4352 (k,q only; staging dead by then)
#define STOT  22016           // 88064 bytes

__global__ __launch_bounds__(192, 2)
void edge_kernel(const int* __restrict__ src, const int* __restrict__ dst,
                 const float* __restrict__ basis, const float* __restrict__ edge_feats,
                 const float* __restrict__ b1, const float* __restrict__ b2, int E) {
    extern __shared__ float sm[];
    unsigned* smu = (unsigned*)sm;
    int t = threadIdx.x;
    int e0 = blockIdx.x * 64;
    int w = t >> 5, lane = t & 31, g = lane >> 2, tq = lane & 3;
    unsigned smb = (unsigned)__cvta_generic_to_shared(sm);

    // ---- stage b2 + per-edge inputs via cp.async (no LDG->STS round trips) ----
    if (t < 192) cpasync16(smb + SB2 * 4 + t * 16, (const float4*)b2 + t);

    for (int idx = t; idx < 512; idx += 192) {
        int el = idx >> 3, q = idx & 7;
        int ee = e0 + el; int ec = ee < E ? ee : E - 1;
        cpasync16(smb + (SEF + el * 32 + q * 4) * 4,
                  (const float4*)edge_feats + (size_t)ec * 8 + q);
        int s = __ldg(src + ec);
        cpasync16(smb + (SFU + el * 32 + q * 4) * 4,
                  (const float4*)fG + (size_t)s * 8 + q);
    }
    for (int idx = t; idx < 1024; idx += 192) {
        int el = idx >> 4, q = idx & 15;
        int ee = e0 + el; int ec = ee < E ? ee : E - 1;
        cpasync16(smb + (SBAS + el * 64 + q * 4) * 4,
                  (const float4*)basis + (size_t)ec * 16 + q);
    }
    cpasync_wait_all();
    __syncthreads();

    // ---- phase A1: tmp = fU x basis (vectorized float4 LDS) ----
    for (int idx = t; idx < 2048; idx += 192) {
        int el = idx >> 5, j = idx & 31;
        int m = j >> 2, pp = j & 3;
        float4 fv = *(const float4*)&sm[SFU + el * 32 + m * 4];
        float4 r0 = *(const float4*)&sm[SBAS + el * 64 + 0 * 16 + pp * 4];
        float4 r1 = *(const float4*)&sm[SBAS + el * 64 + 1 * 16 + pp * 4];
        float4 r2 = *(const float4*)&sm[SBAS + el * 64 + 2 * 16 + pp * 4];
        float4 r3 = *(const float4*)&sm[SBAS + el * 64 + 3 * 16 + pp * 4];
        float o0 = fv.x * r0.x + fv.y * r1.x + fv.z * r2.x + fv.w * r3.x;
        float o1 = fv.x * r0.y + fv.y * r1.y + fv.z * r2.y + fv.w * r3.y;
        float o2 = fv.x * r0.z + fv.y * r1.z + fv.z * r2.z + fv.w * r3.z;
        float o3 = fv.x * r0.w + fv.y * r1.w + fv.z * r2.w + fv.w * r3.w;
        *(float4*)&sm[STMP + el * 132 + j * 4] = make_float4(o0, o1, o2, o3);
    }

    // ---- phase A2: h = relu(ef@w1^T + b1) via split-bf16 MMA ----
    {
        int cur_mt = -1;
        unsigned eAh[2][4], eAl[2][4];
#pragma unroll
        for (int it = 0; it < 6; it++) {
            int p = w + it * 6;                   // (mt, nt) pair index, 32 total
            if (p < 32) {
                int mt = p >> 3, nt = p & 7;
                if (mt != cur_mt) {
                    cur_mt = mt;
#pragma unroll
                    for (int ks = 0; ks < 2; ks++) {
                        float2 x0 = *(const float2*)&sm[SEF + (mt * 16 + g) * 32 + ks * 16 + 2 * tq];
                        float2 x1 = *(const float2*)&sm[SEF + (mt * 16 + g + 8) * 32 + ks * 16 + 2 * tq];
                        float2 x2 = *(const float2*)&sm[SEF + (mt * 16 + g) * 32 + ks * 16 + 8 + 2 * tq];
                        float2 x3 = *(const float2*)&sm[SEF + (mt * 16 + g + 8) * 32 + ks * 16 + 8 + 2 * tq];
                        splitpack(x0.x, x0.y, eAh[ks][0], eAl[ks][0]);
                        splitpack(x1.x, x1.y, eAh[ks][1], eAl[ks][1]);
                        splitpack(x2.x, x2.y, eAh[ks][2], eAl[ks][2]);
                        splitpack(x3.x, x3.y, eAh[ks][3], eAl[ks][3]);
                    }
                }
                float2 bb = __ldg((const float2*)(b1 + nt * 8 + 2 * tq));
                float acc[4] = {bb.x, bb.y, bb.x, bb.y};
#pragma unroll
                for (int ks = 0; ks < 2; ks++) {
                    uint4 bv = __ldg(w1pG + (nt * 2 + ks) * 32 + lane);
                    mma_bf16(acc, eAh[ks], bv.x, bv.y);
                    mma_bf16(acc, eAh[ks], bv.z, bv.w);
                    mma_bf16(acc, eAl[ks], bv.x, bv.y);
                }
                int jp = nt * 4 + tq;
                int r0 = mt * 16 + g;
                unsigned h01, l01, h23, l23;
                splitpack(fmaxf(acc[0], 0.f), fmaxf(acc[1], 0.f), h01, l01);
                splitpack(fmaxf(acc[2], 0.f), fmaxf(acc[3], 0.f), h23, l23);
                smu[SH2H + r0 * 36 + jp] = h01;
                smu[SH2L + r0 * 36 + jp] = l01;
                smu[SH2H + (r0 + 8) * 36 + jp] = h23;
                smu[SH2L + (r0 + 8) * 36 + jp] = l23;
            }
        }
    }
    __syncthreads();

    // ---- phase B: rw GEMM (split bf16, single-acc chains, pipelined) + fused contraction ----
    {
        int ig = w % 3, ehalf = w / 3;
        int i0 = ig * 8 + 2 * tq;

        unsigned Ah[2][4][4], Al[2][4][4];
#pragma unroll
        for (int mt = 0; mt < 2; mt++) {
            int r0 = (ehalf * 2 + mt) * 16 + g;
#pragma unroll
            for (int ks = 0; ks < 4; ks++) {
                Ah[mt][ks][0] = smu[SH2H + r0 * 36 + ks * 8 + tq];
                Ah[mt][ks][1] = smu[SH2H + (r0 + 8) * 36 + ks * 8 + tq];
                Ah[mt][ks][2] = smu[SH2H + r0 * 36 + ks * 8 + 4 + tq];
                Ah[mt][ks][3] = smu[SH2H + (r0 + 8) * 36 + ks * 8 + 4 + tq];
                Al[mt][ks][0] = smu[SH2L + r0 * 36 + ks * 8 + tq];
                Al[mt][ks][1] = smu[SH2L + (r0 + 8) * 36 + ks * 8 + tq];
                Al[mt][ks][2] = smu[SH2L + r0 * 36 + ks * 8 + 4 + tq];
                Al[mt][ks][3] = smu[SH2L + (r0 + 8) * 36 + ks * 8 + 4 + tq];
            }
        }

        unsigned long long cp[2][8];
#pragma unroll
        for (int mt = 0; mt < 2; mt++)
#pragma unroll
            for (int x = 0; x < 8; x++) cp[mt][x] = 0ull;

        const uint4* wp = w2pG + (ig * 4) * 32 + lane;
        uint4 bv[4];
#pragma unroll
        for (int ks = 0; ks < 4; ks++) bv[ks] = __ldg(wp + ks * 32);
        float bzc0 = sm[SB2 + i0 * 32];
        float bzc1 = sm[SB2 + (i0 + 1) * 32];

#pragma unroll 2
        for (int j = 0; j < 32; j++) {
            int jn = (j < 31) ? j + 1 : 31;
            const uint4* wpn = (j < 31) ? wp + 384 : wp;
            uint4 nbv[4];
#pragma unroll
            for (int ks = 0; ks < 4; ks++) nbv[ks] = __ldg(wpn + ks * 32);
            float bzn0 = sm[SB2 + i0 * 32 + jn];
            float bzn1 = sm[SB2 + (i0 + 1) * 32 + jn];

            float mn[2][4];
#pragma unroll
            for (int mt = 0; mt < 2; mt++) {
                mn[mt][0] = bzc0; mn[mt][1] = bzc1; mn[mt][2] = bzc0; mn[mt][3] = bzc1;
            }
#pragma unroll
            for (int ks = 0; ks < 4; ks++)
#pragma unroll
                for (int mt = 0; mt < 2; mt++) {
                    mma_bf16(mn[mt], Ah[mt][ks], bv[ks].x, bv[ks].y);
                    mma_bf16(mn[mt], Ah[mt][ks], bv[ks].z, bv[ks].w);
                    mma_bf16(mn[mt], Al[mt][ks], bv[ks].x, bv[ks].y);
                }
#pragma unroll
            for (int mt = 0; mt < 2; mt++) {
                int er = (ehalf * 2 + mt) * 16 + g;
                float4 t0 = *(const float4*)&sm[STMP + er * 132 + j * 4];
                float4 t1 = *(const float4*)&sm[STMP + (er + 8) * 132 + j * 4];
                unsigned long long ta = packf2(t0.x, t0.y), tb = packf2(t0.z, t0.w);
                unsigned long long tc = packf2(t1.x, t1.y), td = packf2(t1.z, t1.w);
                unsigned long long rp;
                rp = packf2(mn[mt][0], mn[mt][0]); ffma2(cp[mt][0], rp, ta); ffma2(cp[mt][1], rp, tb);
                rp = packf2(mn[mt][1], mn[mt][1]); ffma2(cp[mt][2], rp, ta); ffma2(cp[mt][3], rp, tb);
                rp = packf2(mn[mt][2], mn[mt][2]); ffma2(cp[mt][4], rp, tc); ffma2(cp[mt][5], rp, td);
                rp = packf2(mn[mt][3], mn[mt][3]); ffma2(cp[mt][6], rp, tc); ffma2(cp[mt][7], rp, td);
            }
#pragma unroll
            for (int ks = 0; ks < 4; ks++) bv[ks] = nbv[ks];
            bzc0 = bzn0; bzc1 = bzn1;
            wp = wpn;
        }

        // write conv: k,q (ig<2) -> smem; v (ig==2) -> gmem directly
        if (ig < 2) {
#pragma unroll
            for (int mt = 0; mt < 2; mt++) {
                int er = (ehalf * 2 + mt) * 16 + g;
                float2 a0 = unpackf2(cp[mt][0]), a1 = unpackf2(cp[mt][1]);
                float2 a2 = unpackf2(cp[mt][2]), a3 = unpackf2(cp[mt][3]);
                float2 a4 = unpackf2(cp[mt][4]), a5 = unpackf2(cp[mt][5]);
                float2 a6 = unpackf2(cp[mt][6]), a7 = unpackf2(cp[mt][7]);
                *(float4*)&sm[SCONV + er * 68 + i0 * 4]            = make_float4(a0.x, a0.y, a1.x, a1.y);
                *(float4*)&sm[SCONV + er * 68 + (i0 + 1) * 4]      = make_float4(a2.x, a2.y, a3.x, a3.y);
                *(float4*)&sm[SCONV + (er + 8) * 68 + i0 * 4]      = make_float4(a4.x, a4.y, a5.x, a5.y);
                *(float4*)&sm[SCONV + (er + 8) * 68 + (i0 + 1) * 4] = make_float4(a6.x, a6.y, a7.x, a7.y);
            }
        } else {
#pragma unroll
            for (int mt = 0; mt < 2; mt++) {
                int er = (ehalf * 2 + mt) * 16 + g;
                int v0 = (i0 - 16) * 4;
                float2 a0 = unpackf2(cp[mt][0]), a1 = unpackf2(cp[mt][1]);
                float2 a2 = unpackf2(cp[mt][2]), a3 = unpackf2(cp[mt][3]);
                float2 a4 = unpackf2(cp[mt][4]), a5 = unpackf2(cp[mt][5]);
                float2 a6 = unpackf2(cp[mt][6]), a7 = unpackf2(cp[mt][7]);
                if (e0 + er < E) {
                    *(float4*)&vG[(size_t)(e0 + er) * 32 + v0]     = make_float4(a0.x, a0.y, a1.x, a1.y);
                    *(float4*)&vG[(size_t)(e0 + er) * 32 + v0 + 4] = make_float4(a2.x, a2.y, a3.x, a3.y);
                }
                if (e0 + er + 8 < E) {
                    *(float4*)&vG[(size_t)(e0 + er + 8) * 32 + v0]     = make_float4(a4.x, a4.y, a5.x, a5.y);
                    *(float4*)&vG[(size_t)(e0 + er + 8) * 32 + v0 + 4] = make_float4(a6.x, a6.y, a7.x, a7.y);
                }
            }
        }
    }
    __syncthreads();

    // ---- phase C: scores (max floored at 0 via smaxG invariant) ----
    for (int idx = t; idx < 256; idx += 192) {
        int el2 = idx >> 2, hh = idx & 3;
        float sc = 0.0f;
#pragma unroll
        for (int x = 0; x < 8; x++) {
            int m = 2 * hh + (x >> 2), d = x & 3;
            sc += sm[SCONV + el2 * 68 + m * 4 + d] *
                  sm[SCONV + el2 * 68 + (8 + m) * 4 + d];
        }
        sc *= 0.17677669529663687f;          // 32^-0.5
        sc = sc >= 0.0f ? sc : 0.2f * sc;    // LeakyReLU(0.2)
        int ee = e0 + el2;
        if (ee < E) {
            scoresG[ee * 4 + hh] = sc;
            atomicMaxF(&smaxG[dst[ee] * 4 + hh], sc);
        }
    }
}

// ---------------- softmax accumulate: one thread per edge ----------------
__global__ void attn_kernel(const int* __restrict__ dst, int E) {
    int e = blockIdx.x * blockDim.x + threadIdx.x;
    if (e >= E) return;
    int dn = __ldg(dst + e);
    float4 sc = *(const float4*)(scoresG + (size_t)e * 4);
    float4 mx = *(const float4*)(smaxG + (size_t)dn * 4);
    float ex[4];
    ex[0] = __expf(sc.x - mx.x);
    ex[1] = __expf(sc.y - mx.y);
    ex[2] = __expf(sc.z - mx.z);
    ex[3] = __expf(sc.w - mx.w);
    const float4* vp = (const float4*)(vG + (size_t)e * 32);
    float* pb = accG + (size_t)dn * 48;
#pragma unroll
    for (int h = 0; h < 4; h++) {
        float4 va = vp[h * 2], vb = vp[h * 2 + 1];
        float x = ex[h];
        float* p = pb + h * 12;
        redAdd4(p,     x * va.x, x * va.y, x * va.z, x * va.w);
        redAdd4(p + 4, x * vb.x, x * vb.y, x * vb.z, x * vb.w);
        redAdd1(p + 8, x);
    }
}

// ---------------- node output + scratch restoration ----------------
__global__ void out_kernel(const float* __restrict__ proj_w, float* __restrict__ out, int N) {
    int idx = blockIdx.x * blockDim.x + threadIdx.x;
    if (idx >= N * 4) return;
    int n = idx >> 2, d = idx & 3;
    float den[4];
#pragma unroll
    for (int h = 0; h < 4; h++) den[h] = accG[(size_t)n * 48 + h * 12 + 8];
    float oc[8];
#pragma unroll
    for (int m2 = 0; m2 < 8; m2++) {
        int h = m2 >> 1;
        float dd = den[h];
        float nm = accG[(size_t)n * 48 + h * 12 + (m2 & 1) * 4 + d];
        oc[m2] = dd > 0.0f ? nm / dd : 0.0f;
    }
    int ro = (d == 0) ? 0 : 8;                 // ix2 = [0,1,1,1]
#pragma unroll
    for (int m = 0; m < 8; m++) {
        float r = 0.0f;
#pragma unroll
        for (int m2 = 0; m2 < 8; m2++) r += proj_w[(ro + m) * 8 + m2] * oc[m2];
        out[(size_t)n * 32 + m * 4 + d] = r;
    }
    // restore the scratch invariant for the next launch (program-order after reads)
    float4 z = make_float4(0.f, 0.f, 0.f, 0.f);
    float4* ap = (float4*)(accG + (size_t)n * 48 + d * 12);
    ap[0] = z; ap[1] = z; ap[2] = z;
    smaxG[n * 4 + d] = 0.0f;
}

// ---------------- launcher ----------------
extern "C" void kernel_launch(void* const* d_in, const int* in_sizes, int n_in,
                              void* d_out, int out_size) {
    const int*   src        = (const int*)d_in[0];
    const int*   dst        = (const int*)d_in[1];
    const float* basis      = (const float*)d_in[2];
    const float* features   = (const float*)d_in[3];
    const float* edge_feats = (const float*)d_in[4];
    const float* w1         = (const float*)d_in[5];
    const float* b1         = (const float*)d_in[6];
    const float* w2         = (const float*)d_in[7];
    const float* b2         = (const float*)d_in[8];
    const float* ln_w       = (const float*)d_in[9];
    const float* ln_b       = (const float*)d_in[10];
    const float* proj_w     = (const float*)d_in[11];
    float* out = (float*)d_out;

    int E = in_sizes[0];
    int N = in_sizes[3] / 32;

    int setup_threads = SETUP_P2 + SETUP_P1 + N;
    setup_kernel<<<(setup_threads + 255) / 256, 256>>>(w2, w1, features, ln_w, ln_b, N);

    size_t smbytes = STOT * sizeof(float);
    cudaFuncSetAttribute(edge_kernel, cudaFuncAttributeMaxDynamicSharedMemorySize, (int)smbytes);
    edge_kernel<<<(E + 63) / 64, 192, smbytes>>>(src, dst, basis, edge_feats, b1, b2, E);

    attn_kernel<<<(E + 255) / 256, 256>>>(dst, E);
    out_kernel<<<(N * 4 + 255) / 256, 256>>>(proj_w, out, N);
}

// round 16
// speedup vs baseline: 1.3589x; 1.0078x over previous
#include <cuda_runtime.h>
#include <cuda_bf16.h>
#include <math_constants.h>

#define NN 40000
#define NE 320000

// ---------------- scratch (device globals; zero-initialized at load) ----------------
// Invariant maintained across launches: accG == 0, smaxG == 0 on entry.
__device__ float fG[NN * 32];
__device__ float scoresG[NE * 4];
__device__ float vG[NE * 32];
__device__ float smaxG[NN * 4];
__device__ float accG[NN * 48];   // per (n,h): [0..7]=num, [8]=den, pad
__device__ uint4 w2pG[96 * 4 * 32];
__device__ uint4 w1pG[16 * 32];

// valid when stored value is always >= +0 (sign bit clear), which the 0-floor guarantees
__device__ __forceinline__ void atomicMaxF(float* a, float v) {
    if (v == 0.0f) v = 0.0f;
    if (v >= 0.0f) atomicMax((int*)a, __float_as_int(v));
    else           atomicMin((unsigned int*)a, __float_as_uint(v));
}

__device__ __forceinline__ void redAdd4(float* p, float a, float b, float c, float d) {
    asm volatile("red.global.add.v4.f32 [%0], {%1,%2,%3,%4};"
                 :: "l"(p), "f"(a), "f"(b), "f"(c), "f"(d) : "memory");
}
__device__ __forceinline__ void redAdd1(float* p, float a) {
    asm volatile("red.global.add.f32 [%0], %1;" :: "l"(p), "f"(a) : "memory");
}

__device__ __forceinline__ void cpasync16(unsigned smaddr, const void* g) {
    asm volatile("cp.async.cg.shared.global [%0], [%1], 16;" :: "r"(smaddr), "l"(g) : "memory");
}
__device__ __forceinline__ void cpasync_wait_all() {
    asm volatile("cp.async.commit_group;\ncp.async.wait_group 0;" ::: "memory");
}

__device__ __forceinline__ void mma_bf16(float* c, const unsigned* a, unsigned b0, unsigned b1) {
    asm volatile("mma.sync.aligned.m16n8k16.row.col.f32.bf16.bf16.f32 "
                 "{%0,%1,%2,%3}, {%4,%5,%6,%7}, {%8,%9}, {%0,%1,%2,%3};\n"
                 : "+f"(c[0]), "+f"(c[1]), "+f"(c[2]), "+f"(c[3])
                 : "r"(a[0]), "r"(a[1]), "r"(a[2]), "r"(a[3]), "r"(b0), "r"(b1));
}

// packed fp32x2 helpers (sm_100a FFMA2 path)
__device__ __forceinline__ unsigned long long packf2(float x, float y) {
    unsigned long long r;
    asm("mov.b64 %0, {%1,%2};" : "=l"(r) : "f"(x), "f"(y));
    return r;
}
__device__ __forceinline__ float2 unpackf2(unsigned long long v) {
    float2 r;
    asm("mov.b64 {%0,%1}, %2;" : "=f"(r.x), "=f"(r.y) : "l"(v));
    return r;
}
__device__ __forceinline__ void ffma2(unsigned long long& d, unsigned long long a, unsigned long long b) {
    asm("fma.rn.f32x2 %0, %1, %2, %0;" : "+l"(d) : "l"(a), "l"(b));
}

__device__ __forceinline__ void splitpack(float a, float b, unsigned& hi, unsigned& lo) {
    __nv_bfloat16 ha = __float2bfloat16_rn(a), hb = __float2bfloat16_rn(b);
    __nv_bfloat16 la = __float2bfloat16_rn(a - __bfloat162float(ha));
    __nv_bfloat16 lb = __float2bfloat16_rn(b - __bfloat162float(hb));
    hi = ((unsigned)__bfloat16_as_ushort(hb) << 16) | (unsigned)__bfloat16_as_ushort(ha);
    lo = ((unsigned)__bfloat16_as_ushort(lb) << 16) | (unsigned)__bfloat16_as_ushort(la);
}

// ---------------- merged setup: prep_w2 | prep_w1 | node_ln ----------------
#define SETUP_P2   (768 * 32)              // 24576
#define SETUP_P1   512
__global__ void setup_kernel(const float* __restrict__ w2, const float* __restrict__ w1,
                             const float* __restrict__ features,
                             const float* __restrict__ ln_w, const float* __restrict__ ln_b,
                             int N) {
    int base = blockIdx.x * 256 + threadIdx.x;
    if (base < SETUP_P2) {
        int idx = base;
        int o = idx >> 5, kp = idx & 31;
        unsigned hiu, lou;
        splitpack(w2[o * 64 + 2 * kp], w2[o * 64 + 2 * kp + 1], hiu, lou);
        int i = o >> 5, j = o & 31;
        int tt = j * 3 + (i >> 3);
        int g = i & 7;
        int ks = kp >> 3;
        int tq = kp & 3;
        int half = (kp >> 2) & 1;
        int frag = (tt * 4 + ks) * 32 + g * 4 + tq;
        ((unsigned*)w2pG)[frag * 4 + half]     = hiu;
        ((unsigned*)w2pG)[frag * 4 + 2 + half] = lou;
        return;
    }
    base -= SETUP_P2;
    if (base < SETUP_P1) {
        int idx = base;
        int lane = idx & 31, ksnt = idx >> 5;
        int ks = ksnt & 1, nt = ksnt >> 1;
        int g = lane >> 2, tq = lane & 3;
        int j = nt * 8 + g;
        int k0 = ks * 16 + 2 * tq;
        unsigned h0, l0, h1, l1;
        splitpack(w1[j * 32 + k0],     w1[j * 32 + k0 + 1],     h0, l0);
        splitpack(w1[j * 32 + k0 + 8], w1[j * 32 + k0 + 8 + 1], h1, l1);
        w1pG[(nt * 2 + ks) * 32 + lane] = make_uint4(h0, h1, l0, l1);
        return;
    }
    base -= SETUP_P1;
    if (base < N) {
        int n = base;
        float f[32];
        const float4* fp = (const float4*)(features + (size_t)n * 32);
#pragma unroll
        for (int q = 0; q < 8; q++) {
            float4 v = fp[q];
            f[q * 4 + 0] = v.x; f[q * 4 + 1] = v.y; f[q * 4 + 2] = v.z; f[q * 4 + 3] = v.w;
        }
        float nf[16];
#pragma unroll
        for (int m = 0; m < 8; m++) {
            nf[2 * m]     = sqrtf(f[m * 4] * f[m * 4]);
            nf[2 * m + 1] = sqrtf(f[m * 4 + 1] * f[m * 4 + 1] +
                                  f[m * 4 + 2] * f[m * 4 + 2] +
                                  f[m * 4 + 3] * f[m * 4 + 3]);
        }
        float ratio[16];
#pragma unroll
        for (int g = 0; g < 2; g++) {
            float mu = 0.0f;
#pragma unroll
            for (int b = 0; b < 8; b++) mu += nf[8 * g + b];
            mu *= 0.125f;
            float var = 0.0f;
#pragma unroll
            for (int b = 0; b < 8; b++) { float d = nf[8 * g + b] - mu; var += d * d; }
            var *= 0.125f;
            float rs = rsqrtf(var + 1e-5f);
#pragma unroll
            for (int b = 0; b < 8; b++) {
                float l = (nf[8 * g + b] - mu) * rs * ln_w[b] + ln_b[b];
                l = fmaxf(l, 0.0f);
                ratio[8 * g + b] = l / (nf[8 * g + b] + 1e-8f);
            }
        }
        float4* op = (float4*)(fG + (size_t)n * 32);
#pragma unroll
        for (int m = 0; m < 8; m++) {
            float4 v;
            v.x = f[m * 4 + 0] * ratio[2 * m];
            v.y = f[m * 4 + 1] * ratio[2 * m + 1];
            v.z = f[m * 4 + 2] * ratio[2 * m + 1];
            v.w = f[m * 4 + 3] * ratio[2 * m + 1];
            op[m] = v;
        }
    }
}

// ---------------- fused per-edge kernel: 64 edges / 192 threads ----------------
// smem layout (float/uint indices)
#define SB2   0       // 768
#define STMP  768     // 64*132 -> 9216
#define SH2H  9216    // 64*36 uints -> 11520
#define SH2L  11520   // -> 13824
#define SSTG  13824
#define SEF   (SSTG)          // 64*32
#define SFU   (SSTG + 2048)   // 64*32
#define SBAS  (SSTG + 4096)   // 64*64
#define SCONV (SSTG)          // 64*68 = 4352 (k,q only; staging dead by then)
#define STOT  22016           // 88064 bytes

__global__ __launch_bounds__(192, 2)
void edge_kernel(const int* __restrict__ src, const int* __restrict__ dst,
                 const float* __restrict__ basis, const float* __restrict__ edge_feats,
                 const float* __restrict__ b1, const float* __restrict__ b2, int E) {
    extern __shared__ float sm[];
    unsigned* smu = (unsigned*)sm;
    int t = threadIdx.x;
    int e0 = blockIdx.x * 64;
    int w = t >> 5, lane = t & 31, g = lane >> 2, tq = lane & 3;
    unsigned smb = (unsigned)__cvta_generic_to_shared(sm);

    // ---- stage b2 + per-edge inputs via cp.async (no LDG->STS round trips) ----
    if (t < 192) cpasync16(smb + SB2 * 4 + t * 16, (const float4*)b2 + t);

    for (int idx = t; idx < 512; idx += 192) {
        int el = idx >> 3, q = idx & 7;
        int ee = e0 + el; int ec = ee < E ? ee : E - 1;
        cpasync16(smb + (SEF + el * 32 + q * 4) * 4,
                  (const float4*)edge_feats + (size_t)ec * 8 + q);
        int s = __ldg(src + ec);
        cpasync16(smb + (SFU + el * 32 + q * 4) * 4,
                  (const float4*)fG + (size_t)s * 8 + q);
    }
    for (int idx = t; idx < 1024; idx += 192) {
        int el = idx >> 4, q = idx & 15;
        int ee = e0 + el; int ec = ee < E ? ee : E - 1;
        cpasync16(smb + (SBAS + el * 64 + q * 4) * 4,
                  (const float4*)basis + (size_t)ec * 16 + q);
    }
    cpasync_wait_all();
    __syncthreads();

    // ---- phase A1: tmp = fU x basis (vectorized float4 LDS) ----
    for (int idx = t; idx < 2048; idx += 192) {
        int el = idx >> 5, j = idx & 31;
        int m = j >> 2, pp = j & 3;
        float4 fv = *(const float4*)&sm[SFU + el * 32 + m * 4];
        float4 r0 = *(const float4*)&sm[SBAS + el * 64 + 0 * 16 + pp * 4];
        float4 r1 = *(const float4*)&sm[SBAS + el * 64 + 1 * 16 + pp * 4];
        float4 r2 = *(const float4*)&sm[SBAS + el * 64 + 2 * 16 + pp * 4];
        float4 r3 = *(const float4*)&sm[SBAS + el * 64 + 3 * 16 + pp * 4];
        float o0 = fv.x * r0.x + fv.y * r1.x + fv.z * r2.x + fv.w * r3.x;
        float o1 = fv.x * r0.y + fv.y * r1.y + fv.z * r2.y + fv.w * r3.y;
        float o2 = fv.x * r0.z + fv.y * r1.z + fv.z * r2.z + fv.w * r3.z;
        float o3 = fv.x * r0.w + fv.y * r1.w + fv.z * r2.w + fv.w * r3.w;
        *(float4*)&sm[STMP + el * 132 + j * 4] = make_float4(o0, o1, o2, o3);
    }

    // ---- phase A2: h = relu(ef@w1^T + b1) via split-bf16 MMA ----
    {
        int cur_mt = -1;
        unsigned eAh[2][4], eAl[2][4];
#pragma unroll
        for (int it = 0; it < 6; it++) {
            int p = w + it * 6;                   // (mt, nt) pair index, 32 total
            if (p < 32) {
                int mt = p >> 3, nt = p & 7;
                if (mt != cur_mt) {
                    cur_mt = mt;
#pragma unroll
                    for (int ks = 0; ks < 2; ks++) {
                        float2 x0 = *(const float2*)&sm[SEF + (mt * 16 + g) * 32 + ks * 16 + 2 * tq];
                        float2 x1 = *(const float2*)&sm[SEF + (mt * 16 + g + 8) * 32 + ks * 16 + 2 * tq];
                        float2 x2 = *(const float2*)&sm[SEF + (mt * 16 + g) * 32 + ks * 16 + 8 + 2 * tq];
                        float2 x3 = *(const float2*)&sm[SEF + (mt * 16 + g + 8) * 32 + ks * 16 + 8 + 2 * tq];
                        splitpack(x0.x, x0.y, eAh[ks][0], eAl[ks][0]);
                        splitpack(x1.x, x1.y, eAh[ks][1], eAl[ks][1]);
                        splitpack(x2.x, x2.y, eAh[ks][2], eAl[ks][2]);
                        splitpack(x3.x, x3.y, eAh[ks][3], eAl[ks][3]);
                    }
                }
                float2 bb = __ldg((const float2*)(b1 + nt * 8 + 2 * tq));
                float acc[4] = {bb.x, bb.y, bb.x, bb.y};
#pragma unroll
                for (int ks = 0; ks < 2; ks++) {
                    uint4 bv = __ldg(w1pG + (nt * 2 + ks) * 32 + lane);
                    mma_bf16(acc, eAh[ks], bv.x, bv.y);
                    mma_bf16(acc, eAh[ks], bv.z, bv.w);
                    mma_bf16(acc, eAl[ks], bv.x, bv.y);
                }
                int jp = nt * 4 + tq;
                int r0 = mt * 16 + g;
                unsigned h01, l01, h23, l23;
                splitpack(fmaxf(acc[0], 0.f), fmaxf(acc[1], 0.f), h01, l01);
                splitpack(fmaxf(acc[2], 0.f), fmaxf(acc[3], 0.f), h23, l23);
                smu[SH2H + r0 * 36 + jp] = h01;
                smu[SH2L + r0 * 36 + jp] = l01;
                smu[SH2H + (r0 + 8) * 36 + jp] = h23;
                smu[SH2L + (r0 + 8) * 36 + jp] = l23;
            }
        }
    }
    __syncthreads();

    // ---- phase B: rw GEMM (split bf16, single-acc chains, pipelined) + fused contraction ----
    {
        int ig = w % 3, ehalf = w / 3;
        int i0 = ig * 8 + 2 * tq;

        unsigned Ah[2][4][4], Al[2][4][4];
#pragma unroll
        for (int mt = 0; mt < 2; mt++) {
            int r0 = (ehalf * 2 + mt) * 16 + g;
#pragma unroll
            for (int ks = 0; ks < 4; ks++) {
                Ah[mt][ks][0] = smu[SH2H + r0 * 36 + ks * 8 + tq];
                Ah[mt][ks][1] = smu[SH2H + (r0 + 8) * 36 + ks * 8 + tq];
                Ah[mt][ks][2] = smu[SH2H + r0 * 36 + ks * 8 + 4 + tq];
                Ah[mt][ks][3] = smu[SH2H + (r0 + 8) * 36 + ks * 8 + 4 + tq];
                Al[mt][ks][0] = smu[SH2L + r0 * 36 + ks * 8 + tq];
                Al[mt][ks][1] = smu[SH2L + (r0 + 8) * 36 + ks * 8 + tq];
                Al[mt][ks][2] = smu[SH2L + r0 * 36 + ks * 8 + 4 + tq];
                Al[mt][ks][3] = smu[SH2L + (r0 + 8) * 36 + ks * 8 + 4 + tq];
            }
        }

        unsigned long long cp[2][8];
#pragma unroll
        for (int mt = 0; mt < 2; mt++)
#pragma unroll
            for (int x = 0; x < 8; x++) cp[mt][x] = 0ull;

        const uint4* wp = w2pG + (ig * 4) * 32 + lane;
        uint4 bv[4];
#pragma unroll
        for (int ks = 0; ks < 4; ks++) bv[ks] = __ldg(wp + ks * 32);
        float bzc0 = sm[SB2 + i0 * 32];
        float bzc1 = sm[SB2 + (i0 + 1) * 32];

#pragma unroll 2
        for (int j = 0; j < 32; j++) {
            int jn = (j < 31) ? j + 1 : 31;
            const uint4* wpn = (j < 31) ? wp + 384 : wp;
            uint4 nbv[4];
#pragma unroll
            for (int ks = 0; ks < 4; ks++) nbv[ks] = __ldg(wpn + ks * 32);
            float bzn0 = sm[SB2 + i0 * 32 + jn];
            float bzn1 = sm[SB2 + (i0 + 1) * 32 + jn];

            float mn[2][4];
#pragma unroll
            for (int mt = 0; mt < 2; mt++) {
                mn[mt][0] = bzc0; mn[mt][1] = bzc1; mn[mt][2] = bzc0; mn[mt][3] = bzc1;
            }
#pragma unroll
            for (int ks = 0; ks < 4; ks++)
#pragma unroll
                for (int mt = 0; mt < 2; mt++) {
                    mma_bf16(mn[mt], Ah[mt][ks], bv[ks].x, bv[ks].y);
                    mma_bf16(mn[mt], Ah[mt][ks], bv[ks].z, bv[ks].w);
                    mma_bf16(mn[mt], Al[mt][ks], bv[ks].x, bv[ks].y);
                }
#pragma unroll
            for (int mt = 0; mt < 2; mt++) {
                int er = (ehalf * 2 + mt) * 16 + g;
                float4 t0 = *(const float4*)&sm[STMP + er * 132 + j * 4];
                float4 t1 = *(const float4*)&sm[STMP + (er + 8) * 132 + j * 4];
                unsigned long long ta = packf2(t0.x, t0.y), tb = packf2(t0.z, t0.w);
                unsigned long long tc = packf2(t1.x, t1.y), td = packf2(t1.z, t1.w);
                unsigned long long rp;
                rp = packf2(mn[mt][0], mn[mt][0]); ffma2(cp[mt][0], rp, ta); ffma2(cp[mt][1], rp, tb);
                rp = packf2(mn[mt][1], mn[mt][1]); ffma2(cp[mt][2], rp, ta); ffma2(cp[mt][3], rp, tb);
                rp = packf2(mn[mt][2], mn[mt][2]); ffma2(cp[mt][4], rp, tc); ffma2(cp[mt][5], rp, td);
                rp = packf2(mn[mt][3], mn[mt][3]); ffma2(cp[mt][6], rp, tc); ffma2(cp[mt][7], rp, td);
            }
#pragma unroll
            for (int ks = 0; ks < 4; ks++) bv[ks] = nbv[ks];
            bzc0 = bzn0; bzc1 = bzn1;
            wp = wpn;
        }

        // write conv: k,q (ig<2) -> smem; v (ig==2) -> gmem directly
        if (ig < 2) {
#pragma unroll
            for (int mt = 0; mt < 2; mt++) {
                int er = (ehalf * 2 + mt) * 16 + g;
                float2 a0 = unpackf2(cp[mt][0]), a1 = unpackf2(cp[mt][1]);
                float2 a2 = unpackf2(cp[mt][2]), a3 = unpackf2(cp[mt][3]);
                float2 a4 = unpackf2(cp[mt][4]), a5 = unpackf2(cp[mt][5]);
                float2 a6 = unpackf2(cp[mt][6]), a7 = unpackf2(cp[mt][7]);
                *(float4*)&sm[SCONV + er * 68 + i0 * 4]            = make_float4(a0.x, a0.y, a1.x, a1.y);
                *(float4*)&sm[SCONV + er * 68 + (i0 + 1) * 4]      = make_float4(a2.x, a2.y, a3.x, a3.y);
                *(float4*)&sm[SCONV + (er + 8) * 68 + i0 * 4]      = make_float4(a4.x, a4.y, a5.x, a5.y);
                *(float4*)&sm[SCONV + (er + 8) * 68 + (i0 + 1) * 4] = make_float4(a6.x, a6.y, a7.x, a7.y);
            }
        } else {
#pragma unroll
            for (int mt = 0; mt < 2; mt++) {
                int er = (ehalf * 2 + mt) * 16 + g;
                int v0 = (i0 - 16) * 4;
                float2 a0 = unpackf2(cp[mt][0]), a1 = unpackf2(cp[mt][1]);
                float2 a2 = unpackf2(cp[mt][2]), a3 = unpackf2(cp[mt][3]);
                float2 a4 = unpackf2(cp[mt][4]), a5 = unpackf2(cp[mt][5]);
                float2 a6 = unpackf2(cp[mt][6]), a7 = unpackf2(cp[mt][7]);
                if (e0 + er < E) {
                    *(float4*)&vG[(size_t)(e0 + er) * 32 + v0]     = make_float4(a0.x, a0.y, a1.x, a1.y);
                    *(float4*)&vG[(size_t)(e0 + er) * 32 + v0 + 4] = make_float4(a2.x, a2.y, a3.x, a3.y);
                }
                if (e0 + er + 8 < E) {
                    *(float4*)&vG[(size_t)(e0 + er + 8) * 32 + v0]     = make_float4(a4.x, a4.y, a5.x, a5.y);
                    *(float4*)&vG[(size_t)(e0 + er + 8) * 32 + v0 + 4] = make_float4(a6.x, a6.y, a7.x, a7.y);
                }
            }
        }
    }
    __syncthreads();

    // ---- phase C: scores (vectorized float4 LDS; max floored at 0) ----
    for (int idx = t; idx < 256; idx += 192) {
        int el2 = idx >> 2, hh = idx & 3;
        const float* cb = &sm[SCONV + el2 * 68];
        float4 k0 = *(const float4*)(cb + (2 * hh) * 4);
        float4 k1 = *(const float4*)(cb + (2 * hh + 1) * 4);
        float4 q0 = *(const float4*)(cb + (8 + 2 * hh) * 4);
        float4 q1 = *(const float4*)(cb + (9 + 2 * hh) * 4);
        float sc = k0.x * q0.x + k0.y * q0.y + k0.z * q0.z + k0.w * q0.w
                 + k1.x * q1.x + k1.y * q1.y + k1.z * q1.z + k1.w * q1.w;
        sc *= 0.17677669529663687f;          // 32^-0.5
        sc = sc >= 0.0f ? sc : 0.2f * sc;    // LeakyReLU(0.2)
        int ee = e0 + el2;
        if (ee < E) {
            scoresG[ee * 4 + hh] = sc;
            atomicMaxF(&smaxG[dst[ee] * 4 + hh], sc);
        }
    }
}

// ---------------- softmax accumulate: one thread per edge ----------------
__global__ void attn_kernel(const int* __restrict__ dst, int E) {
    int e = blockIdx.x * blockDim.x + threadIdx.x;
    if (e >= E) return;
    int dn = __ldg(dst + e);
    float4 sc = __ldg((const float4*)(scoresG + (size_t)e * 4));
    float4 mx = __ldg((const float4*)(smaxG + (size_t)dn * 4));
    float ex[4];
    ex[0] = __expf(sc.x - mx.x);
    ex[1] = __expf(sc.y - mx.y);
    ex[2] = __expf(sc.z - mx.z);
    ex[3] = __expf(sc.w - mx.w);
    const float4* vp = (const float4*)(vG + (size_t)e * 32);
    float* pb = accG + (size_t)dn * 48;
#pragma unroll
    for (int h = 0; h < 4; h++) {
        float4 va = __ldg(vp + h * 2), vb = __ldg(vp + h * 2 + 1);
        float x = ex[h];
        float* p = pb + h * 12;
        redAdd4(p,     x * va.x, x * va.y, x * va.z, x * va.w);
        redAdd4(p + 4, x * vb.x, x * vb.y, x * vb.z, x * vb.w);
        redAdd1(p + 8, x);
    }
}

// ---------------- node output + scratch restoration ----------------
__global__ void out_kernel(const float* __restrict__ proj_w, float* __restrict__ out, int N) {
    int idx = blockIdx.x * blockDim.x + threadIdx.x;
    if (idx >= N * 4) return;
    int n = idx >> 2, d = idx & 3;
    float den[4];
#pragma unroll
    for (int h = 0; h < 4; h++) den[h] = accG[(size_t)n * 48 + h * 12 + 8];
    float oc[8];
#pragma unroll
    for (int m2 = 0; m2 < 8; m2++) {
        int h = m2 >> 1;
        float dd = den[h];
        float nm = accG[(size_t)n * 48 + h * 12 + (m2 & 1) * 4 + d];
        oc[m2] = dd > 0.0f ? nm / dd : 0.0f;
    }
    int ro = (d == 0) ? 0 : 8;                 // ix2 = [0,1,1,1]
#pragma unroll
    for (int m = 0; m < 8; m++) {
        float r = 0.0f;
#pragma unroll
        for (int m2 = 0; m2 < 8; m2++) r += proj_w[(ro + m) * 8 + m2] * oc[m2];
        out[(size_t)n * 32 + m * 4 + d] = r;
    }
    // restore the scratch invariant for the next launch (program-order after reads)
    float4 z = make_float4(0.f, 0.f, 0.f, 0.f);
    float4* ap = (float4*)(accG + (size_t)n * 48 + d * 12);
    ap[0] = z; ap[1] = z; ap[2] = z;
    smaxG[n * 4 + d] = 0.0f;
}

// ---------------- launcher ----------------
extern "C" void kernel_launch(void* const* d_in, const int* in_sizes, int n_in,
                              void* d_out, int out_size) {
    const int*   src        = (const int*)d_in[0];
    const int*   dst        = (const int*)d_in[1];
    const float* basis      = (const float*)d_in[2];
    const float* features   = (const float*)d_in[3];
    const float* edge_feats = (const float*)d_in[4];
    const float* w1         = (const float*)d_in[5];
    const float* b1         = (const float*)d_in[6];
    const float* w2         = (const float*)d_in[7];
    const float* b2         = (const float*)d_in[8];
    const float* ln_w       = (const float*)d_in[9];
    const float* ln_b       = (const float*)d_in[10];
    const float* proj_w     = (const float*)d_in[11];
    float* out = (float*)d_out;

    int E = in_sizes[0];
    int N = in_sizes[3] / 32;

    int setup_threads = SETUP_P2 + SETUP_P1 + N;
    setup_kernel<<<(setup_threads + 255) / 256, 256>>>(w2, w1, features, ln_w, ln_b, N);

    size_t smbytes = STOT * sizeof(float);
    cudaFuncSetAttribute(edge_kernel, cudaFuncAttributeMaxDynamicSharedMemorySize, (int)smbytes);
    edge_kernel<<<(E + 63) / 64, 192, smbytes>>>(src, dst, basis, edge_feats, b1, b2, E);

    attn_kernel<<<(E + 255) / 256, 256>>>(dst, E);
    out_kernel<<<(N * 4 + 255) / 256, 256>>>(proj_w, out, N);
}

// round 17
// speedup vs baseline: 1.3743x; 1.0113x over previous
#include <cuda_runtime.h>
#include <cuda_bf16.h>
#include <math_constants.h>

#define NN 40000
#define NE 320000

// ---------------- scratch (device globals; zero-initialized at load) ----------------
// Invariant maintained across launches: accG == 0, smaxG == 0 on entry.
__device__ float fG[NN * 32];
__device__ float scoresG[NE * 4];
__device__ float vG[NE * 32];
__device__ float smaxG[NN * 4];
__device__ float accG[NN * 36];   // per n: [0..31] num (h*8+slot), [32..35] den[h]
__device__ uint4 w2pG[96 * 4 * 32];
__device__ uint4 w1pG[16 * 32];

// valid when stored value is always >= +0 (sign bit clear), which the 0-floor guarantees
__device__ __forceinline__ void atomicMaxF(float* a, float v) {
    if (v == 0.0f) v = 0.0f;
    if (v >= 0.0f) atomicMax((int*)a, __float_as_int(v));
    else           atomicMin((unsigned int*)a, __float_as_uint(v));
}

__device__ __forceinline__ void redAdd4(float* p, float a, float b, float c, float d) {
    asm volatile("red.global.add.v4.f32 [%0], {%1,%2,%3,%4};"
                 :: "l"(p), "f"(a), "f"(b), "f"(c), "f"(d) : "memory");
}

__device__ __forceinline__ void cpasync16(unsigned smaddr, const void* g) {
    asm volatile("cp.async.cg.shared.global [%0], [%1], 16;" :: "r"(smaddr), "l"(g) : "memory");
}
__device__ __forceinline__ void cpasync_wait_all() {
    asm volatile("cp.async.commit_group;\ncp.async.wait_group 0;" ::: "memory");
}

__device__ __forceinline__ void mma_bf16(float* c, const unsigned* a, unsigned b0, unsigned b1) {
    asm volatile("mma.sync.aligned.m16n8k16.row.col.f32.bf16.bf16.f32 "
                 "{%0,%1,%2,%3}, {%4,%5,%6,%7}, {%8,%9}, {%0,%1,%2,%3};\n"
                 : "+f"(c[0]), "+f"(c[1]), "+f"(c[2]), "+f"(c[3])
                 : "r"(a[0]), "r"(a[1]), "r"(a[2]), "r"(a[3]), "r"(b0), "r"(b1));
}

// packed fp32x2 helpers (sm_100a FFMA2 path)
__device__ __forceinline__ unsigned long long packf2(float x, float y) {
    unsigned long long r;
    asm("mov.b64 %0, {%1,%2};" : "=l"(r) : "f"(x), "f"(y));
    return r;
}
__device__ __forceinline__ float2 unpackf2(unsigned long long v) {
    float2 r;
    asm("mov.b64 {%0,%1}, %2;" : "=f"(r.x), "=f"(r.y) : "l"(v));
    return r;
}
__device__ __forceinline__ void ffma2(unsigned long long& d, unsigned long long a, unsigned long long b) {
    asm("fma.rn.f32x2 %0, %1, %2, %0;" : "+l"(d) : "l"(a), "l"(b));
}

__device__ __forceinline__ void splitpack(float a, float b, unsigned& hi, unsigned& lo) {
    __nv_bfloat16 ha = __float2bfloat16_rn(a), hb = __float2bfloat16_rn(b);
    __nv_bfloat16 la = __float2bfloat16_rn(a - __bfloat162float(ha));
    __nv_bfloat16 lb = __float2bfloat16_rn(b - __bfloat162float(hb));
    hi = ((unsigned)__bfloat16_as_ushort(hb) << 16) | (unsigned)__bfloat16_as_ushort(ha);
    lo = ((unsigned)__bfloat16_as_ushort(lb) << 16) | (unsigned)__bfloat16_as_ushort(la);
}

// ---------------- merged setup: prep_w2 | prep_w1 | node_ln ----------------
#define SETUP_P2   (768 * 32)              // 24576
#define SETUP_P1   512
__global__ void setup_kernel(const float* __restrict__ w2, const float* __restrict__ w1,
                             const float* __restrict__ features,
                             const float* __restrict__ ln_w, const float* __restrict__ ln_b,
                             int N) {
    int base = blockIdx.x * 256 + threadIdx.x;
    if (base < SETUP_P2) {
        int idx = base;
        int o = idx >> 5, kp = idx & 31;
        unsigned hiu, lou;
        splitpack(w2[o * 64 + 2 * kp], w2[o * 64 + 2 * kp + 1], hiu, lou);
        int i = o >> 5, j = o & 31;
        int tt = j * 3 + (i >> 3);
        int g = i & 7;
        int ks = kp >> 3;
        int tq = kp & 3;
        int half = (kp >> 2) & 1;
        int frag = (tt * 4 + ks) * 32 + g * 4 + tq;
        ((unsigned*)w2pG)[frag * 4 + half]     = hiu;
        ((unsigned*)w2pG)[frag * 4 + 2 + half] = lou;
        return;
    }
    base -= SETUP_P2;
    if (base < SETUP_P1) {
        int idx = base;
        int lane = idx & 31, ksnt = idx >> 5;
        int ks = ksnt & 1, nt = ksnt >> 1;
        int g = lane >> 2, tq = lane & 3;
        int j = nt * 8 + g;
        int k0 = ks * 16 + 2 * tq;
        unsigned h0, l0, h1, l1;
        splitpack(w1[j * 32 + k0],     w1[j * 32 + k0 + 1],     h0, l0);
        splitpack(w1[j * 32 + k0 + 8], w1[j * 32 + k0 + 8 + 1], h1, l1);
        w1pG[(nt * 2 + ks) * 32 + lane] = make_uint4(h0, h1, l0, l1);
        return;
    }
    base -= SETUP_P1;
    if (base < N) {
        int n = base;
        float f[32];
        const float4* fp = (const float4*)(features + (size_t)n * 32);
#pragma unroll
        for (int q = 0; q < 8; q++) {
            float4 v = fp[q];
            f[q * 4 + 0] = v.x; f[q * 4 + 1] = v.y; f[q * 4 + 2] = v.z; f[q * 4 + 3] = v.w;
        }
        float nf[16];
#pragma unroll
        for (int m = 0; m < 8; m++) {
            nf[2 * m]     = sqrtf(f[m * 4] * f[m * 4]);
            nf[2 * m + 1] = sqrtf(f[m * 4 + 1] * f[m * 4 + 1] +
                                  f[m * 4 + 2] * f[m * 4 + 2] +
                                  f[m * 4 + 3] * f[m * 4 + 3]);
        }
        float ratio[16];
#pragma unroll
        for (int g = 0; g < 2; g++) {
            float mu = 0.0f;
#pragma unroll
            for (int b = 0; b < 8; b++) mu += nf[8 * g + b];
            mu *= 0.125f;
            float var = 0.0f;
#pragma unroll
            for (int b = 0; b < 8; b++) { float d = nf[8 * g + b] - mu; var += d * d; }
            var *= 0.125f;
            float rs = rsqrtf(var + 1e-5f);
#pragma unroll
            for (int b = 0; b < 8; b++) {
                float l = (nf[8 * g + b] - mu) * rs * ln_w[b] + ln_b[b];
                l = fmaxf(l, 0.0f);
                ratio[8 * g + b] = l / (nf[8 * g + b] + 1e-8f);
            }
        }
        float4* op = (float4*)(fG + (size_t)n * 32);
#pragma unroll
        for (int m = 0; m < 8; m++) {
            float4 v;
            v.x = f[m * 4 + 0] * ratio[2 * m];
            v.y = f[m * 4 + 1] * ratio[2 * m + 1];
            v.z = f[m * 4 + 2] * ratio[2 * m + 1];
            v.w = f[m * 4 + 3] * ratio[2 * m + 1];
            op[m] = v;
        }
    }
}

// ---------------- fused per-edge kernel: 64 edges / 192 threads ----------------
// smem layout (float/uint indices)
#define SB2   0       // 768
#define STMP  768     // 64*132 -> 9216
#define SH2H  9216    // 64*36 uints -> 11520
#define SH2L  11520   // -> 13824
#define SSTG  13824
#define SEF   (SSTG)          // 64*32
#define SFU   (SSTG + 2048)   // 64*32
#define SBAS  (SSTG + 4096)   // 64*64
#define SCONV (SSTG)          // 64*68 = 4352 (k,q only; staging dead by then)
#define STOT  22016           // 88064 bytes

__global__ __launch_bounds__(192, 2)
void edge_kernel(const int* __restrict__ src, const int* __restrict__ dst,
                 const float* __restrict__ basis, const float* __restrict__ edge_feats,
                 const float* __restrict__ b1, const float* __restrict__ b2, int E) {
    extern __shared__ float sm[];
    unsigned* smu = (unsigned*)sm;
    int t = threadIdx.x;
    int e0 = blockIdx.x * 64;
    int w = t >> 5, lane = t & 31, g = lane >> 2, tq = lane & 3;
    unsigned smb = (unsigned)__cvta_generic_to_shared(sm);

    // ---- stage b2 + per-edge inputs via cp.async (no LDG->STS round trips) ----
    if (t < 192) cpasync16(smb + SB2 * 4 + t * 16, (const float4*)b2 + t);

    for (int idx = t; idx < 512; idx += 192) {
        int el = idx >> 3, q = idx & 7;
        int ee = e0 + el; int ec = ee < E ? ee : E - 1;
        cpasync16(smb + (SEF + el * 32 + q * 4) * 4,
                  (const float4*)edge_feats + (size_t)ec * 8 + q);
        int s = __ldg(src + ec);
        cpasync16(smb + (SFU + el * 32 + q * 4) * 4,
                  (const float4*)fG + (size_t)s * 8 + q);
    }
    for (int idx = t; idx < 1024; idx += 192) {
        int el = idx >> 4, q = idx & 15;
        int ee = e0 + el; int ec = ee < E ? ee : E - 1;
        cpasync16(smb + (SBAS + el * 64 + q * 4) * 4,
                  (const float4*)basis + (size_t)ec * 16 + q);
    }
    cpasync_wait_all();
    __syncthreads();

    // ---- phase A1: tmp = fU x basis (vectorized float4 LDS) ----
    for (int idx = t; idx < 2048; idx += 192) {
        int el = idx >> 5, j = idx & 31;
        int m = j >> 2, pp = j & 3;
        float4 fv = *(const float4*)&sm[SFU + el * 32 + m * 4];
        float4 r0 = *(const float4*)&sm[SBAS + el * 64 + 0 * 16 + pp * 4];
        float4 r1 = *(const float4*)&sm[SBAS + el * 64 + 1 * 16 + pp * 4];
        float4 r2 = *(const float4*)&sm[SBAS + el * 64 + 2 * 16 + pp * 4];
        float4 r3 = *(const float4*)&sm[SBAS + el * 64 + 3 * 16 + pp * 4];
        float o0 = fv.x * r0.x + fv.y * r1.x + fv.z * r2.x + fv.w * r3.x;
        float o1 = fv.x * r0.y + fv.y * r1.y + fv.z * r2.y + fv.w * r3.y;
        float o2 = fv.x * r0.z + fv.y * r1.z + fv.z * r2.z + fv.w * r3.z;
        float o3 = fv.x * r0.w + fv.y * r1.w + fv.z * r2.w + fv.w * r3.w;
        *(float4*)&sm[STMP + el * 132 + j * 4] = make_float4(o0, o1, o2, o3);
    }

    // ---- phase A2: h = relu(ef@w1^T + b1) via split-bf16 MMA ----
    {
        int cur_mt = -1;
        unsigned eAh[2][4], eAl[2][4];
#pragma unroll
        for (int it = 0; it < 6; it++) {
            int p = w + it * 6;                   // (mt, nt) pair index, 32 total
            if (p < 32) {
                int mt = p >> 3, nt = p & 7;
                if (mt != cur_mt) {
                    cur_mt = mt;
#pragma unroll
                    for (int ks = 0; ks < 2; ks++) {
                        float2 x0 = *(const float2*)&sm[SEF + (mt * 16 + g) * 32 + ks * 16 + 2 * tq];
                        float2 x1 = *(const float2*)&sm[SEF + (mt * 16 + g + 8) * 32 + ks * 16 + 2 * tq];
                        float2 x2 = *(const float2*)&sm[SEF + (mt * 16 + g) * 32 + ks * 16 + 8 + 2 * tq];
                        float2 x3 = *(const float2*)&sm[SEF + (mt * 16 + g + 8) * 32 + ks * 16 + 8 + 2 * tq];
                        splitpack(x0.x, x0.y, eAh[ks][0], eAl[ks][0]);
                        splitpack(x1.x, x1.y, eAh[ks][1], eAl[ks][1]);
                        splitpack(x2.x, x2.y, eAh[ks][2], eAl[ks][2]);
                        splitpack(x3.x, x3.y, eAh[ks][3], eAl[ks][3]);
                    }
                }
                float2 bb = __ldg((const float2*)(b1 + nt * 8 + 2 * tq));
                float acc[4] = {bb.x, bb.y, bb.x, bb.y};
#pragma unroll
                for (int ks = 0; ks < 2; ks++) {
                    uint4 bv = __ldg(w1pG + (nt * 2 + ks) * 32 + lane);
                    mma_bf16(acc, eAh[ks], bv.x, bv.y);
                    mma_bf16(acc, eAh[ks], bv.z, bv.w);
                    mma_bf16(acc, eAl[ks], bv.x, bv.y);
                }
                int jp = nt * 4 + tq;
                int r0 = mt * 16 + g;
                unsigned h01, l01, h23, l23;
                splitpack(fmaxf(acc[0], 0.f), fmaxf(acc[1], 0.f), h01, l01);
                splitpack(fmaxf(acc[2], 0.f), fmaxf(acc[3], 0.f), h23, l23);
                smu[SH2H + r0 * 36 + jp] = h01;
                smu[SH2L + r0 * 36 + jp] = l01;
                smu[SH2H + (r0 + 8) * 36 + jp] = h23;
                smu[SH2L + (r0 + 8) * 36 + jp] = l23;
            }
        }
    }
    __syncthreads();

    // ---- phase B: rw GEMM (split bf16, single-acc chains, pipelined) + fused contraction ----
    {
        int ig = w % 3, ehalf = w / 3;
        int i0 = ig * 8 + 2 * tq;

        unsigned Ah[2][4][4], Al[2][4][4];
#pragma unroll
        for (int mt = 0; mt < 2; mt++) {
            int r0 = (ehalf * 2 + mt) * 16 + g;
#pragma unroll
            for (int ks = 0; ks < 4; ks++) {
                Ah[mt][ks][0] = smu[SH2H + r0 * 36 + ks * 8 + tq];
                Ah[mt][ks][1] = smu[SH2H + (r0 + 8) * 36 + ks * 8 + tq];
                Ah[mt][ks][2] = smu[SH2H + r0 * 36 + ks * 8 + 4 + tq];
                Ah[mt][ks][3] = smu[SH2H + (r0 + 8) * 36 + ks * 8 + 4 + tq];
                Al[mt][ks][0] = smu[SH2L + r0 * 36 + ks * 8 + tq];
                Al[mt][ks][1] = smu[SH2L + (r0 + 8) * 36 + ks * 8 + tq];
                Al[mt][ks][2] = smu[SH2L + r0 * 36 + ks * 8 + 4 + tq];
                Al[mt][ks][3] = smu[SH2L + (r0 + 8) * 36 + ks * 8 + 4 + tq];
            }
        }

        unsigned long long cp[2][8];
#pragma unroll
        for (int mt = 0; mt < 2; mt++)
#pragma unroll
            for (int x = 0; x < 8; x++) cp[mt][x] = 0ull;

        const uint4* wp = w2pG + (ig * 4) * 32 + lane;
        uint4 bv[4];
#pragma unroll
        for (int ks = 0; ks < 4; ks++) bv[ks] = __ldg(wp + ks * 32);
        float bzc0 = sm[SB2 + i0 * 32];
        float bzc1 = sm[SB2 + (i0 + 1) * 32];

#pragma unroll 2
        for (int j = 0; j < 32; j++) {
            int jn = (j < 31) ? j + 1 : 31;
            const uint4* wpn = (j < 31) ? wp + 384 : wp;
            uint4 nbv[4];
#pragma unroll
            for (int ks = 0; ks < 4; ks++) nbv[ks] = __ldg(wpn + ks * 32);
            float bzn0 = sm[SB2 + i0 * 32 + jn];
            float bzn1 = sm[SB2 + (i0 + 1) * 32 + jn];

            float mn[2][4];
#pragma unroll
            for (int mt = 0; mt < 2; mt++) {
                mn[mt][0] = bzc0; mn[mt][1] = bzc1; mn[mt][2] = bzc0; mn[mt][3] = bzc1;
            }
#pragma unroll
            for (int ks = 0; ks < 4; ks++)
#pragma unroll
                for (int mt = 0; mt < 2; mt++) {
                    mma_bf16(mn[mt], Ah[mt][ks], bv[ks].x, bv[ks].y);
                    mma_bf16(mn[mt], Ah[mt][ks], bv[ks].z, bv[ks].w);
                    mma_bf16(mn[mt], Al[mt][ks], bv[ks].x, bv[ks].y);
                }
#pragma unroll
            for (int mt = 0; mt < 2; mt++) {
                int er = (ehalf * 2 + mt) * 16 + g;
                float4 t0 = *(const float4*)&sm[STMP + er * 132 + j * 4];
                float4 t1 = *(const float4*)&sm[STMP + (er + 8) * 132 + j * 4];
                unsigned long long ta = packf2(t0.x, t0.y), tb = packf2(t0.z, t0.w);
                unsigned long long tc = packf2(t1.x, t1.y), td = packf2(t1.z, t1.w);
                unsigned long long rp;
                rp = packf2(mn[mt][0], mn[mt][0]); ffma2(cp[mt][0], rp, ta); ffma2(cp[mt][1], rp, tb);
                rp = packf2(mn[mt][1], mn[mt][1]); ffma2(cp[mt][2], rp, ta); ffma2(cp[mt][3], rp, tb);
                rp = packf2(mn[mt][2], mn[mt][2]); ffma2(cp[mt][4], rp, tc); ffma2(cp[mt][5], rp, td);
                rp = packf2(mn[mt][3], mn[mt][3]); ffma2(cp[mt][6], rp, tc); ffma2(cp[mt][7], rp, td);
            }
#pragma unroll
            for (int ks = 0; ks < 4; ks++) bv[ks] = nbv[ks];
            bzc0 = bzn0; bzc1 = bzn1;
            wp = wpn;
        }

        // write conv: k,q (ig<2) -> smem; v (ig==2) -> gmem directly
        if (ig < 2) {
#pragma unroll
            for (int mt = 0; mt < 2; mt++) {
                int er = (ehalf * 2 + mt) * 16 + g;
                float2 a0 = unpackf2(cp[mt][0]), a1 = unpackf2(cp[mt][1]);
                float2 a2 = unpackf2(cp[mt][2]), a3 = unpackf2(cp[mt][3]);
                float2 a4 = unpackf2(cp[mt][4]), a5 = unpackf2(cp[mt][5]);
                float2 a6 = unpackf2(cp[mt][6]), a7 = unpackf2(cp[mt][7]);
                *(float4*)&sm[SCONV + er * 68 + i0 * 4]            = make_float4(a0.x, a0.y, a1.x, a1.y);
                *(float4*)&sm[SCONV + er * 68 + (i0 + 1) * 4]      = make_float4(a2.x, a2.y, a3.x, a3.y);
                *(float4*)&sm[SCONV + (er + 8) * 68 + i0 * 4]      = make_float4(a4.x, a4.y, a5.x, a5.y);
                *(float4*)&sm[SCONV + (er + 8) * 68 + (i0 + 1) * 4] = make_float4(a6.x, a6.y, a7.x, a7.y);
            }
        } else {
#pragma unroll
            for (int mt = 0; mt < 2; mt++) {
                int er = (ehalf * 2 + mt) * 16 + g;
                int v0 = (i0 - 16) * 4;
                float2 a0 = unpackf2(cp[mt][0]), a1 = unpackf2(cp[mt][1]);
                float2 a2 = unpackf2(cp[mt][2]), a3 = unpackf2(cp[mt][3]);
                float2 a4 = unpackf2(cp[mt][4]), a5 = unpackf2(cp[mt][5]);
                float2 a6 = unpackf2(cp[mt][6]), a7 = unpackf2(cp[mt][7]);
                if (e0 + er < E) {
                    *(float4*)&vG[(size_t)(e0 + er) * 32 + v0]     = make_float4(a0.x, a0.y, a1.x, a1.y);
                    *(float4*)&vG[(size_t)(e0 + er) * 32 + v0 + 4] = make_float4(a2.x, a2.y, a3.x, a3.y);
                }
                if (e0 + er + 8 < E) {
                    *(float4*)&vG[(size_t)(e0 + er + 8) * 32 + v0]     = make_float4(a4.x, a4.y, a5.x, a5.y);
                    *(float4*)&vG[(size_t)(e0 + er + 8) * 32 + v0 + 4] = make_float4(a6.x, a6.y, a7.x, a7.y);
                }
            }
        }
    }
    __syncthreads();

    // ---- phase C: scores (vectorized float4 LDS; max floored at 0) ----
    for (int idx = t; idx < 256; idx += 192) {
        int el2 = idx >> 2, hh = idx & 3;
        const float* cb = &sm[SCONV + el2 * 68];
        float4 k0 = *(const float4*)(cb + (2 * hh) * 4);
        float4 k1 = *(const float4*)(cb + (2 * hh + 1) * 4);
        float4 q0 = *(const float4*)(cb + (8 + 2 * hh) * 4);
        float4 q1 = *(const float4*)(cb + (9 + 2 * hh) * 4);
        float sc = k0.x * q0.x + k0.y * q0.y + k0.z * q0.z + k0.w * q0.w
                 + k1.x * q1.x + k1.y * q1.y + k1.z * q1.z + k1.w * q1.w;
        sc *= 0.17677669529663687f;          // 32^-0.5
        sc = sc >= 0.0f ? sc : 0.2f * sc;    // LeakyReLU(0.2)
        int ee = e0 + el2;
        if (ee < E) {
            scoresG[ee * 4 + hh] = sc;
            atomicMaxF(&smaxG[dst[ee] * 4 + hh], sc);
        }
    }
}

// ---------------- softmax accumulate: one thread per edge, 9 red.v4 ----------------
__global__ void attn_kernel(const int* __restrict__ dst, int E) {
    int e = blockIdx.x * blockDim.x + threadIdx.x;
    if (e >= E) return;
    int dn = __ldg(dst + e);
    float4 sc = __ldg((const float4*)(scoresG + (size_t)e * 4));
    float4 mx = __ldg((const float4*)(smaxG + (size_t)dn * 4));
    float ex[4];
    ex[0] = __expf(sc.x - mx.x);
    ex[1] = __expf(sc.y - mx.y);
    ex[2] = __expf(sc.z - mx.z);
    ex[3] = __expf(sc.w - mx.w);
    const float4* vp = (const float4*)(vG + (size_t)e * 32);
    float* pb = accG + (size_t)dn * 36;
#pragma unroll
    for (int h = 0; h < 4; h++) {
        float4 va = __ldg(vp + h * 2), vb = __ldg(vp + h * 2 + 1);
        float x = ex[h];
        float* p = pb + h * 8;
        redAdd4(p,     x * va.x, x * va.y, x * va.z, x * va.w);
        redAdd4(p + 4, x * vb.x, x * vb.y, x * vb.z, x * vb.w);
    }
    redAdd4(pb + 32, ex[0], ex[1], ex[2], ex[3]);
}

// ---------------- node output + scratch restoration ----------------
__global__ void out_kernel(const float* __restrict__ proj_w, float* __restrict__ out, int N) {
    int idx = blockIdx.x * blockDim.x + threadIdx.x;
    if (idx >= N * 4) return;
    int n = idx >> 2, d = idx & 3;
    float4 den4 = *(const float4*)(accG + (size_t)n * 36 + 32);
    float den[4] = {den4.x, den4.y, den4.z, den4.w};
    float oc[8];
#pragma unroll
    for (int m2 = 0; m2 < 8; m2++) {
        int h = m2 >> 1;
        float dd = den[h];
        float nm = accG[(size_t)n * 36 + h * 8 + (m2 & 1) * 4 + d];
        oc[m2] = dd > 0.0f ? nm / dd : 0.0f;
    }
    int ro = (d == 0) ? 0 : 8;                 // ix2 = [0,1,1,1]
#pragma unroll
    for (int m = 0; m < 8; m++) {
        float r = 0.0f;
#pragma unroll
        for (int m2 = 0; m2 < 8; m2++) r += proj_w[(ro + m) * 8 + m2] * oc[m2];
        out[(size_t)n * 32 + m * 4 + d] = r;
    }
    // restore the scratch invariant for the next launch (program-order after reads):
    // thread d zeroes num[h=d] (8 floats) + den[d] + smax[d]  -> covers all 36 + 4
    float4 z = make_float4(0.f, 0.f, 0.f, 0.f);
    float4* ap = (float4*)(accG + (size_t)n * 36 + d * 8);
    ap[0] = z; ap[1] = z;
    accG[(size_t)n * 36 + 32 + d] = 0.0f;
    smaxG[n * 4 + d] = 0.0f;
}

// ---------------- launcher ----------------
extern "C" void kernel_launch(void* const* d_in, const int* in_sizes, int n_in,
                              void* d_out, int out_size) {
    const int*   src        = (const int*)d_in[0];
    const int*   dst        = (const int*)d_in[1];
    const float* basis      = (const float*)d_in[2];
    const float* features   = (const float*)d_in[3];
    const float* edge_feats = (const float*)d_in[4];
    const float* w1         = (const float*)d_in[5];
    const float* b1         = (const float*)d_in[6];
    const float* w2         = (const float*)d_in[7];
    const float* b2         = (const float*)d_in[8];
    const float* ln_w       = (const float*)d_in[9];
    const float* ln_b       = (const float*)d_in[10];
    const float* proj_w     = (const float*)d_in[11];
    float* out = (float*)d_out;

    int E = in_sizes[0];
    int N = in_sizes[3] / 32;

    int setup_threads = SETUP_P2 + SETUP_P1 + N;
    setup_kernel<<<(setup_threads + 255) / 256, 256>>>(w2, w1, features, ln_w, ln_b, N);

    size_t smbytes = STOT * sizeof(float);
    cudaFuncSetAttribute(edge_kernel, cudaFuncAttributeMaxDynamicSharedMemorySize, (int)smbytes);
    edge_kernel<<<(E + 63) / 64, 192, smbytes>>>(src, dst, basis, edge_feats, b1, b2, E);

    attn_kernel<<<(E + 255) / 256, 256>>>(dst, E);
    out_kernel<<<(N * 4 + 255) / 256, 256>>>(proj_w, out, N);
}